// round 5
// baseline (speedup 1.0000x reference)
#include <cuda_runtime.h>
#include <cuda_bf16.h>
#include <math.h>
#include <stdint.h>

#define BB 32
#define SS 512
#define HH 2048
#define NHH 8
#define HD 256
#define MR (BB*SS)           // 16384
#define H3 (3*HH)            // 6144
#define H4 (4*HH)            // 8192
#define NHEADS (BB*NHH)      // 256
#define NSROWS (NHEADS*SS)
#define SCH ((long)SS*SS)
#define QSTR ((long)SS*H3)
#define VTS ((long)HD*SS)

// ---------------- scratch (device globals) ------------------------------
__device__ __align__(16) float g_sc [(size_t)NHEADS*SS*SS];   // fp32 scores
__device__ __align__(16) float g_t1 [(size_t)MR*HH];
__device__ __align__(16) float g_t2 [(size_t)MR*HH];
__device__ __align__(16) float g_h1 [(size_t)MR*HH];
// bf16 hi/lo pools
__device__ __align__(16) __nv_bfloat16 g_pAh[(size_t)MR*H4];
__device__ __align__(16) __nv_bfloat16 g_pAl[(size_t)MR*H4];
__device__ __align__(16) __nv_bfloat16 g_pBh[(size_t)NHEADS*SS*SS];
__device__ __align__(16) __nv_bfloat16 g_pBl[(size_t)NHEADS*SS*SS];
__device__ __align__(16) __nv_bfloat16 g_vh [(size_t)MR*HH];
__device__ __align__(16) __nv_bfloat16 g_vl [(size_t)MR*HH];
__device__ __align__(16) __nv_bfloat16 g_wh [(size_t)H4*HH];
__device__ __align__(16) __nv_bfloat16 g_wl [(size_t)H4*HH];

// ---------------- helpers ------------------------------------------------
__device__ __forceinline__ void bsplit(float v, __nv_bfloat16& h, __nv_bfloat16& l){
    h = __float2bfloat16(v);
    l = __float2bfloat16(v - __bfloat162float(h));
}
__device__ __forceinline__ void cpa16(uint32_t s, const void* g){
    asm volatile("cp.async.cg.shared.global [%0], [%1], 16;\n" :: "r"(s), "l"(g));
}
__device__ __forceinline__ void ldsm4(uint32_t addr, uint32_t* r){
    asm volatile("ldmatrix.sync.aligned.m8n8.x4.shared.b16 {%0,%1,%2,%3}, [%4];\n"
        : "=r"(r[0]),"=r"(r[1]),"=r"(r[2]),"=r"(r[3]) : "r"(addr));
}
__device__ __forceinline__ void mma16816(float* d, const uint32_t* a, const uint32_t* b){
    asm volatile("mma.sync.aligned.m16n8k16.row.col.f32.bf16.bf16.f32 "
        "{%0,%1,%2,%3}, {%4,%5,%6,%7}, {%8,%9}, {%0,%1,%2,%3};\n"
        : "+f"(d[0]),"+f"(d[1]),"+f"(d[2]),"+f"(d[3])
        : "r"(a[0]),"r"(a[1]),"r"(a[2]),"r"(a[3]), "r"(b[0]),"r"(b[1]));
}

// ---------------- elementwise kernels ------------------------------------
__global__ void gather_pe_split(const float* __restrict__ emb,
                                const float* __restrict__ pe,
                                const int*   __restrict__ idx,
                                __nv_bfloat16* __restrict__ xh,
                                __nv_bfloat16* __restrict__ xl)
{
    long i = (long)blockIdx.x * blockDim.x + threadIdx.x;
    const long n4 = (long)MR * HH / 4;
    if (i >= n4) return;
    long row = i / (HH/4);
    long c4  = i - row * (HH/4);
    float4 e = ((const float4*)emb)[i];
    const float4* p = (const float4*)(pe + (long)idx[row]*HH);
    float4 pv = p[c4];
    float v[4] = {e.x+pv.x, e.y+pv.y, e.z+pv.z, e.w+pv.w};
    __nv_bfloat16 h[4], l[4];
    #pragma unroll
    for (int j = 0; j < 4; j++) bsplit(v[j], h[j], l[j]);
    ((__nv_bfloat162*)xh)[2*i]   = __nv_bfloat162(h[0],h[1]);
    ((__nv_bfloat162*)xh)[2*i+1] = __nv_bfloat162(h[2],h[3]);
    ((__nv_bfloat162*)xl)[2*i]   = __nv_bfloat162(l[0],l[1]);
    ((__nv_bfloat162*)xl)[2*i+1] = __nv_bfloat162(l[2],l[3]);
}

__global__ void split_kernel(const float* __restrict__ x,
                             __nv_bfloat16* __restrict__ hi,
                             __nv_bfloat16* __restrict__ lo, long n4)
{
    long i = (long)blockIdx.x * blockDim.x + threadIdx.x;
    if (i >= n4) return;
    float4 v = ((const float4*)x)[i];
    __nv_bfloat16 h[4], l[4];
    bsplit(v.x,h[0],l[0]); bsplit(v.y,h[1],l[1]);
    bsplit(v.z,h[2],l[2]); bsplit(v.w,h[3],l[3]);
    ((__nv_bfloat162*)hi)[2*i]   = __nv_bfloat162(h[0],h[1]);
    ((__nv_bfloat162*)hi)[2*i+1] = __nv_bfloat162(h[2],h[3]);
    ((__nv_bfloat162*)lo)[2*i]   = __nv_bfloat162(l[0],l[1]);
    ((__nv_bfloat162*)lo)[2*i+1] = __nv_bfloat162(l[2],l[3]);
}

__global__ void ln_split_kernel(const float* __restrict__ in,
                                const float* __restrict__ g,
                                const float* __restrict__ b,
                                float* __restrict__ of,
                                __nv_bfloat16* __restrict__ oh,
                                __nv_bfloat16* __restrict__ ol)
{
    __shared__ float sh[8];
    long row = blockIdx.x;
    const float* x = in + row * (long)HH;
    int t = threadIdx.x;
    float v[8];
    float s = 0.f;
    #pragma unroll
    for (int i = 0; i < 8; i++) { v[i] = x[t + i*256]; s += v[i]; }
    #pragma unroll
    for (int o = 16; o > 0; o >>= 1) s += __shfl_xor_sync(0xffffffffu, s, o);
    if ((t & 31) == 0) sh[t >> 5] = s;
    __syncthreads();
    float mean = (sh[0]+sh[1]+sh[2]+sh[3]+sh[4]+sh[5]+sh[6]+sh[7]) * (1.f/HH);
    __syncthreads();
    float sq = 0.f;
    #pragma unroll
    for (int i = 0; i < 8; i++) { float d = v[i]-mean; sq += d*d; }
    #pragma unroll
    for (int o = 16; o > 0; o >>= 1) sq += __shfl_xor_sync(0xffffffffu, sq, o);
    if ((t & 31) == 0) sh[t >> 5] = sq;
    __syncthreads();
    float rstd = rsqrtf((sh[0]+sh[1]+sh[2]+sh[3]+sh[4]+sh[5]+sh[6]+sh[7]) * (1.f/HH) + 1e-5f);
    long base = row * (long)HH;
    #pragma unroll
    for (int i = 0; i < 8; i++) {
        int c = t + i*256;
        float y = (v[i]-mean)*rstd*g[c] + b[c];
        if (of) of[base + c] = y;
        __nv_bfloat16 h, l; bsplit(y, h, l);
        oh[base + c] = h; ol[base + c] = l;
    }
}

__global__ void l2norm_kernel(const float* __restrict__ in, float* __restrict__ out)
{
    __shared__ float sh[8];
    long row = blockIdx.x;
    const float* x = in + row * (long)HH;
    int t = threadIdx.x;
    float v[8];
    float sq = 0.f;
    #pragma unroll
    for (int i = 0; i < 8; i++) { v[i] = x[t + i*256]; sq += v[i]*v[i]; }
    #pragma unroll
    for (int o = 16; o > 0; o >>= 1) sq += __shfl_xor_sync(0xffffffffu, sq, o);
    if ((t & 31) == 0) sh[t >> 5] = sq;
    __syncthreads();
    float tot = sh[0]+sh[1]+sh[2]+sh[3]+sh[4]+sh[5]+sh[6]+sh[7];
    float inv = 1.f / fmaxf(sqrtf(tot), 1e-12f);
    float* orow = out + row * (long)HH;
    #pragma unroll
    for (int i = 0; i < 8; i++) { int c = t + i*256; orow[c] = v[i]*inv; }
}

__global__ void softmax_split(const float* __restrict__ s,
                              __nv_bfloat16* __restrict__ oh,
                              __nv_bfloat16* __restrict__ ol)
{
    long warp = ((long)blockIdx.x * blockDim.x + threadIdx.x) >> 5;
    int lane = threadIdx.x & 31;
    if (warp >= (long)NSROWS) return;
    const float* row = s + warp * (long)SS;
    float vals[16];
    float mx = -1e30f;
    #pragma unroll
    for (int i = 0; i < 16; i++) { vals[i] = row[lane + i*32]; mx = fmaxf(mx, vals[i]); }
    #pragma unroll
    for (int o = 16; o > 0; o >>= 1) mx = fmaxf(mx, __shfl_xor_sync(0xffffffffu, mx, o));
    float sum = 0.f;
    #pragma unroll
    for (int i = 0; i < 16; i++) { vals[i] = __expf(vals[i]-mx); sum += vals[i]; }
    #pragma unroll
    for (int o = 16; o > 0; o >>= 1) sum += __shfl_xor_sync(0xffffffffu, sum, o);
    float inv = 1.f / sum;
    long base = warp * (long)SS;
    #pragma unroll
    for (int i = 0; i < 16; i++) {
        float y = vals[i]*inv;
        __nv_bfloat16 h, l; bsplit(y, h, l);
        oh[base + lane + i*32] = h; ol[base + lane + i*32] = l;
    }
}

__global__ void vtrans_kernel(const __nv_bfloat16* __restrict__ qh,
                              const __nv_bfloat16* __restrict__ ql,
                              __nv_bfloat16* __restrict__ vh,
                              __nv_bfloat16* __restrict__ vl)
{
    __shared__ uint32_t tile[32][33];
    int bh = blockIdx.z;
    int b = bh >> 3, h = bh & 7;
    int s0 = blockIdx.x * 32, d0 = blockIdx.y * 32;
    int tx = threadIdx.x, ty = threadIdx.y;     // (32,8)
    long ibase = (long)b*QSTR + 2*HH + (long)h*HD;
    #pragma unroll
    for (int r = 0; r < 32; r += 8) {
        long idx = ibase + (long)(s0+ty+r)*H3 + d0+tx;
        uint32_t u = ((uint32_t)__bfloat16_as_ushort(qh[idx]) << 16)
                   |  (uint32_t)__bfloat16_as_ushort(ql[idx]);
        tile[ty+r][tx] = u;
    }
    __syncthreads();
    long obase = (long)bh * VTS;
    #pragma unroll
    for (int r = 0; r < 32; r += 8) {
        uint32_t u = tile[tx][ty+r];
        long o = obase + (long)(d0+ty+r)*SS + s0+tx;
        vh[o] = __ushort_as_bfloat16((unsigned short)(u >> 16));
        vl[o] = __ushort_as_bfloat16((unsigned short)(u & 0xffff));
    }
}

// ---------------- mma.sync bf16-split GEMM -------------------------------
// 3-stage cp.async ring, prefetch distance 2, ONE barrier per K-chunk.
#define STG_SZ 65536
#define SM_AH 0
#define SM_AL 16384
#define SM_BH 32768
#define SM_BL 49152
#define NSTG 3
#define SMEMSZ (NSTG*STG_SZ)

template<int ACT, bool RESID, int OMODE>
__global__ void __launch_bounds__(256, 1) tc_gemm(
    const __nv_bfloat16* __restrict__ Ah, const __nv_bfloat16* __restrict__ Al,
    const __nv_bfloat16* __restrict__ Bh, const __nv_bfloat16* __restrict__ Bl,
    const float* __restrict__ bias, const float* __restrict__ Rr,
    float* __restrict__ Cf,
    __nv_bfloat16* __restrict__ Ch, __nv_bfloat16* __restrict__ Cl,
    int K, int lda, int ldb, int ldc,
    long offA1, long offA2, long offB1, long offB2, long offC1, long offC2,
    float alpha)
{
    extern __shared__ char smem[];
    uint32_t sb = (uint32_t)__cvta_generic_to_shared(smem);
    int tid = threadIdx.x;
    int z = blockIdx.z, zb = z >> 3, zh = z & 7;
    long ash = zb*offA1 + zh*offA2;
    long bsh = zb*offB1 + zh*offB2;
    long csh = zb*offC1 + zh*offC2;
    Ah += ash; Al += ash; Bh += bsh; Bl += bsh;
    long m0 = (long)blockIdx.y * 128;
    long n0 = (long)blockIdx.x * 128;

    int l = tid & 31, w = tid >> 5;
    int wm = w & 1, wn = w >> 1;

    uint32_t a_off[4], b_off[2];
    #pragma unroll
    for (int mi = 0; mi < 4; mi++){
        int row = wm*64 + mi*16 + (l & 15);
        a_off[mi] = row*128 + (((l >> 4) << 4) ^ ((row & 7) << 4));
    }
    #pragma unroll
    for (int nj = 0; nj < 2; nj++){
        int row = wn*32 + nj*16 + (l & 7) + ((l & 16) ? 8 : 0);
        b_off[nj] = row*128 + ((((l >> 3) & 1) << 4) ^ ((row & 7) << 4));
    }

    float acc[4][4][4];
    #pragma unroll
    for (int a = 0; a < 4; a++)
        #pragma unroll
        for (int b = 0; b < 4; b++)
            #pragma unroll
            for (int c = 0; c < 4; c++) acc[a][b][c] = 0.f;

    const int NC = K >> 6;
    auto load_chunk = [&](int st, int kc){
        uint32_t base = sb + st*STG_SZ;
        long k0 = (long)kc << 6;
        #pragma unroll
        for (int i = 0; i < 4; i++){
            int task = tid + i*256;
            int row = task >> 3, seg = task & 7;
            uint32_t so = row*128 + ((seg*16) ^ ((row & 7) << 4));
            long ga = (m0 + row) * (long)lda + k0 + seg*8;
            long gb = (n0 + row) * (long)ldb + k0 + seg*8;
            cpa16(base + SM_AH + so, Ah + ga);
            cpa16(base + SM_AL + so, Al + ga);
            cpa16(base + SM_BH + so, Bh + gb);
            cpa16(base + SM_BL + so, Bl + gb);
        }
        asm volatile("cp.async.commit_group;\n" ::: "memory");
    };

    load_chunk(0, 0);
    load_chunk(1, 1);

    int st = 0;
    for (int c = 0; c < NC; c++){
        if (c + 1 < NC)
            asm volatile("cp.async.wait_group 1;\n" ::: "memory");
        else
            asm volatile("cp.async.wait_group 0;\n" ::: "memory");
        __syncthreads();    // stage c ready to all; compute(c-1) done in all warps
        if (c + 2 < NC){
            int st2 = st + 2; if (st2 >= NSTG) st2 -= NSTG;
            load_chunk(st2, c + 2);
        }
        uint32_t bAh = sb + st*STG_SZ + SM_AH;
        uint32_t bAl = sb + st*STG_SZ + SM_AL;
        uint32_t bBh = sb + st*STG_SZ + SM_BH;
        uint32_t bBl = sb + st*STG_SZ + SM_BL;
        #pragma unroll
        for (int ks = 0; ks < 4; ks++){
            uint32_t kx = (uint32_t)ks << 5;
            uint32_t ahf[4][4], alf[4][4], bhf[2][4], blf[2][4];
            #pragma unroll
            for (int mi = 0; mi < 4; mi++){
                ldsm4(bAh + (a_off[mi] ^ kx), ahf[mi]);
                ldsm4(bAl + (a_off[mi] ^ kx), alf[mi]);
            }
            #pragma unroll
            for (int nj = 0; nj < 2; nj++){
                ldsm4(bBh + (b_off[nj] ^ kx), bhf[nj]);
                ldsm4(bBl + (b_off[nj] ^ kx), blf[nj]);
            }
            #pragma unroll
            for (int mi = 0; mi < 4; mi++)
                #pragma unroll
                for (int nj = 0; nj < 4; nj++){
                    const uint32_t* b2h = &bhf[nj>>1][(nj&1)*2];
                    const uint32_t* b2l = &blf[nj>>1][(nj&1)*2];
                    mma16816(acc[mi][nj], ahf[mi], b2h);
                    mma16816(acc[mi][nj], alf[mi], b2h);
                    mma16816(acc[mi][nj], ahf[mi], b2l);
                }
        }
        if (++st >= NSTG) st = 0;
    }

    // epilogue
    int r0 = (int)m0 + wm*64 + (l >> 2);
    int c0 = (int)n0 + wn*32 + 2*(l & 3);
    #pragma unroll
    for (int mi = 0; mi < 4; mi++){
        #pragma unroll
        for (int half = 0; half < 2; half++){
            long row = r0 + mi*16 + half*8;
            #pragma unroll
            for (int nj = 0; nj < 4; nj++){
                int cc = c0 + nj*8;
                long o = csh + row*(long)ldc + cc;
                float v0 = acc[mi][nj][half*2+0] * alpha;
                float v1 = acc[mi][nj][half*2+1] * alpha;
                if (bias){ v0 += bias[cc]; v1 += bias[cc+1]; }
                if (ACT == 1){
                    v0 = 0.5f*v0*(1.f + erff(v0*0.70710678118654752f));
                    v1 = 0.5f*v1*(1.f + erff(v1*0.70710678118654752f));
                } else if (ACT == 2){
                    v0 = fmaxf(v0, 0.f); v1 = fmaxf(v1, 0.f);
                }
                if (RESID){
                    const float* rp = Rr + o;
                    v0 += rp[0]; v1 += rp[1];
                }
                if (OMODE == 0){
                    *(float2*)(Cf + o) = make_float2(v0, v1);
                } else {
                    __nv_bfloat16 h0,l0,h1,l1;
                    bsplit(v0,h0,l0); bsplit(v1,h1,l1);
                    *(__nv_bfloat162*)(Ch + o) = __nv_bfloat162(h0,h1);
                    *(__nv_bfloat162*)(Cl + o) = __nv_bfloat162(l0,l1);
                }
            }
        }
    }
}

// ---------------- host orchestration -------------------------------------
extern "C" void kernel_launch(void* const* d_in, const int* in_sizes, int n_in,
                              void* d_out, int out_size)
{
    (void)in_sizes; (void)n_in; (void)out_size;
    const float* emb  = (const float*)d_in[0];
    const int*   tidx = (const int*)  d_in[1];
    const float* pe   = (const float*)d_in[2];
    const float* inw  = (const float*)d_in[3];
    const float* inb  = (const float*)d_in[4];
    const float* ow   = (const float*)d_in[5];
    const float* ob   = (const float*)d_in[6];
    const float* ln1g = (const float*)d_in[7];
    const float* ln1b = (const float*)d_in[8];
    const float* f1w  = (const float*)d_in[9];
    const float* f1b  = (const float*)d_in[10];
    const float* f2w  = (const float*)d_in[11];
    const float* f2b  = (const float*)d_in[12];
    const float* ln2g = (const float*)d_in[13];
    const float* ln2b = (const float*)d_in[14];
    const float* te1w = (const float*)d_in[15];
    const float* te1b = (const float*)d_in[16];
    const float* te2w = (const float*)d_in[17];
    const float* te2b = (const float*)d_in[18];
    const float* pr1w = (const float*)d_in[19];
    const float* pr1b = (const float*)d_in[20];
    const float* pr2w = (const float*)d_in[21];
    const float* pr2b = (const float*)d_in[22];
    float* out = (float*)d_out;

    float *sc,*t1,*t2,*h1;
    __nv_bfloat16 *pAh,*pAl,*pBh,*pBl,*vh,*vl,*wh,*wl;
    cudaGetSymbolAddress((void**)&sc,  g_sc);
    cudaGetSymbolAddress((void**)&t1,  g_t1);
    cudaGetSymbolAddress((void**)&t2,  g_t2);
    cudaGetSymbolAddress((void**)&h1,  g_h1);
    cudaGetSymbolAddress((void**)&pAh, g_pAh);
    cudaGetSymbolAddress((void**)&pAl, g_pAl);
    cudaGetSymbolAddress((void**)&pBh, g_pBh);
    cudaGetSymbolAddress((void**)&pBl, g_pBl);
    cudaGetSymbolAddress((void**)&vh,  g_vh);
    cudaGetSymbolAddress((void**)&vl,  g_vl);
    cudaGetSymbolAddress((void**)&wh,  g_wh);
    cudaGetSymbolAddress((void**)&wl,  g_wl);

    cudaFuncSetAttribute(tc_gemm<0,false,1>, cudaFuncAttributeMaxDynamicSharedMemorySize, SMEMSZ);
    cudaFuncSetAttribute(tc_gemm<0,false,0>, cudaFuncAttributeMaxDynamicSharedMemorySize, SMEMSZ);
    cudaFuncSetAttribute(tc_gemm<0,true ,0>, cudaFuncAttributeMaxDynamicSharedMemorySize, SMEMSZ);
    cudaFuncSetAttribute(tc_gemm<1,false,1>, cudaFuncAttributeMaxDynamicSharedMemorySize, SMEMSZ);
    cudaFuncSetAttribute(tc_gemm<2,false,1>, cudaFuncAttributeMaxDynamicSharedMemorySize, SMEMSZ);

    auto wsplit = [&](const float* src, long n){
        split_kernel<<<(unsigned)((n/4 + 255) / 256), 256>>>(src, wh, wl, n/4);
    };

    // 1) x = emb + pe[idx]  -> poolB
    gather_pe_split<<<(MR*(HH/4) + 255)/256, 256>>>(emb, pe, tidx, pBh, pBl);

    // 2) qkv = x @ in_proj_w^T + b  -> poolA (hi/lo)
    wsplit(inw, (long)H3*HH);
    tc_gemm<0,false,1><<<dim3(H3/128, MR/128, 1), 256, SMEMSZ>>>(
        pBh, pBl, wh, wl, inb, 0, 0, pAh, pAl,
        HH, HH, HH, H3, 0,0,0,0,0,0, 1.f);

    // 3) scores = (Q@K^T)/16 -> fp32 sc   (batched over 256 heads)
    tc_gemm<0,false,0><<<dim3(SS/128, SS/128, NHEADS), 256, SMEMSZ>>>(
        pAh, pAl, pAh + HH, pAl + HH, 0, 0, sc, 0, 0,
        HD, H3, H3, SS, QSTR, HD, QSTR, HD, 8*SCH, SCH, 0.0625f);

    // 4) Vt transpose (from qkv hi/lo), softmax -> poolB
    vtrans_kernel<<<dim3(SS/32, HD/32, NHEADS), dim3(32,8)>>>(pAh, pAl, vh, vl);
    softmax_split<<<NSROWS/8, 256>>>(sc, pBh, pBl);

    // 5) o = A @ V -> poolA (hi/lo)
    tc_gemm<0,false,1><<<dim3(HD/128, SS/128, NHEADS), 256, SMEMSZ>>>(
        pBh, pBl, vh, vl, 0, 0, 0, pAh, pAl,
        SS, SS, SS, HH, 8*SCH, SCH, 8*VTS, VTS, (long)SS*HH, HD, 1.f);

    // 6) t1 = o @ out_proj_w^T + b + emb -> fp32
    wsplit(ow, (long)HH*HH);
    tc_gemm<0,true,0><<<dim3(HH/128, MR/128, 1), 256, SMEMSZ>>>(
        pAh, pAl, wh, wl, ob, emb, t1, 0, 0,
        HH, HH, HH, HH, 0,0,0,0,0,0, 1.f);

    // 7) h1 = LN(t1) -> fp32 (residual) + poolB (hi/lo)
    ln_split_kernel<<<MR, 256>>>(t1, ln1g, ln1b, h1, pBh, pBl);

    // 8) mid = gelu(h1 @ ffn_w1^T + b1) -> poolA (hi/lo)
    wsplit(f1w, (long)H4*HH);
    tc_gemm<1,false,1><<<dim3(H4/128, MR/128, 1), 256, SMEMSZ>>>(
        pBh, pBl, wh, wl, f1b, 0, 0, pAh, pAl,
        HH, HH, HH, H4, 0,0,0,0,0,0, 1.f);

    // 9) t2 = mid @ ffn_w2^T + b2 + h1 -> fp32
    wsplit(f2w, (long)HH*H4);
    tc_gemm<0,true,0><<<dim3(HH/128, MR/128, 1), 256, SMEMSZ>>>(
        pAh, pAl, wh, wl, f2b, h1, t2, 0, 0,
        H4, H4, H4, HH, 0,0,0,0,0,0, 1.f);

    // 10) h2 = LN(t2) -> poolB (hi/lo only)
    ln_split_kernel<<<MR, 256>>>(t2, ln2g, ln2b, 0, pBh, pBl);

    // 11) relu(h2 @ te_w1^T + b1) -> poolA
    wsplit(te1w, (long)HH*HH);
    tc_gemm<2,false,1><<<dim3(HH/128, MR/128, 1), 256, SMEMSZ>>>(
        pBh, pBl, wh, wl, te1b, 0, 0, pAh, pAl,
        HH, HH, HH, HH, 0,0,0,0,0,0, 1.f);

    // 12) te2 -> poolB
    wsplit(te2w, (long)HH*HH);
    tc_gemm<0,false,1><<<dim3(HH/128, MR/128, 1), 256, SMEMSZ>>>(
        pAh, pAl, wh, wl, te2b, 0, 0, pBh, pBl,
        HH, HH, HH, HH, 0,0,0,0,0,0, 1.f);

    // 13) relu(pr1) -> poolA
    wsplit(pr1w, (long)HH*HH);
    tc_gemm<2,false,1><<<dim3(HH/128, MR/128, 1), 256, SMEMSZ>>>(
        pBh, pBl, wh, wl, pr1b, 0, 0, pAh, pAl,
        HH, HH, HH, HH, 0,0,0,0,0,0, 1.f);

    // 14) pr2 -> fp32 t1
    wsplit(pr2w, (long)HH*HH);
    tc_gemm<0,false,0><<<dim3(HH/128, MR/128, 1), 256, SMEMSZ>>>(
        pAh, pAl, wh, wl, pr2b, 0, t1, 0, 0,
        HH, HH, HH, HH, 0,0,0,0,0,0, 1.f);

    // 15) out = pr / max(||pr||, 1e-12)
    l2norm_kernel<<<MR, 256>>>(t1, out);
}

// round 6
// speedup vs baseline: 1.0790x; 1.0790x over previous
#include <cuda_runtime.h>
#include <cuda_bf16.h>
#include <math.h>
#include <stdint.h>

#define BB 32
#define SS 512
#define HH 2048
#define NHH 8
#define HD 256
#define MR (BB*SS)           // 16384
#define H3 (3*HH)            // 6144
#define H4 (4*HH)            // 8192
#define NHEADS (BB*NHH)      // 256
#define NSROWS (NHEADS*SS)
#define SCH ((long)SS*SS)
#define QSTR ((long)SS*H3)
#define VTS ((long)HD*SS)

// ---------------- scratch (device globals) ------------------------------
__device__ __align__(16) float g_sc [(size_t)NHEADS*SS*SS];   // fp32 scores
__device__ __align__(16) float g_t1 [(size_t)MR*HH];
__device__ __align__(16) float g_t2 [(size_t)MR*HH];
__device__ __align__(16) float g_h1 [(size_t)MR*HH];
// bf16 hi/lo pools
__device__ __align__(16) __nv_bfloat16 g_pAh[(size_t)MR*H4];
__device__ __align__(16) __nv_bfloat16 g_pAl[(size_t)MR*H4];
__device__ __align__(16) __nv_bfloat16 g_pBh[(size_t)NHEADS*SS*SS];
__device__ __align__(16) __nv_bfloat16 g_pBl[(size_t)NHEADS*SS*SS];
__device__ __align__(16) __nv_bfloat16 g_vh [(size_t)MR*HH];
__device__ __align__(16) __nv_bfloat16 g_vl [(size_t)MR*HH];
__device__ __align__(16) __nv_bfloat16 g_wh [(size_t)H4*HH];
__device__ __align__(16) __nv_bfloat16 g_wl [(size_t)H4*HH];
// folded te2*pr1 weight + bias
__device__ __align__(16) __nv_bfloat16 g_fwh[(size_t)HH*HH];
__device__ __align__(16) __nv_bfloat16 g_fwl[(size_t)HH*HH];
__device__ __align__(16) float g_fb[HH];

// ---------------- helpers ------------------------------------------------
__device__ __forceinline__ void bsplit(float v, __nv_bfloat16& h, __nv_bfloat16& l){
    h = __float2bfloat16(v);
    l = __float2bfloat16(v - __bfloat162float(h));
}
__device__ __forceinline__ void cpa16(uint32_t s, const void* g){
    asm volatile("cp.async.cg.shared.global [%0], [%1], 16;\n" :: "r"(s), "l"(g));
}
__device__ __forceinline__ void ldsm4(uint32_t addr, uint32_t* r){
    asm volatile("ldmatrix.sync.aligned.m8n8.x4.shared.b16 {%0,%1,%2,%3}, [%4];\n"
        : "=r"(r[0]),"=r"(r[1]),"=r"(r[2]),"=r"(r[3]) : "r"(addr));
}
__device__ __forceinline__ void mma16816(float* d, const uint32_t* a, const uint32_t* b){
    asm volatile("mma.sync.aligned.m16n8k16.row.col.f32.bf16.bf16.f32 "
        "{%0,%1,%2,%3}, {%4,%5,%6,%7}, {%8,%9}, {%0,%1,%2,%3};\n"
        : "+f"(d[0]),"+f"(d[1]),"+f"(d[2]),"+f"(d[3])
        : "r"(a[0]),"r"(a[1]),"r"(a[2]),"r"(a[3]), "r"(b[0]),"r"(b[1]));
}

// ---------------- elementwise kernels ------------------------------------
__global__ void gather_pe_split(const float* __restrict__ emb,
                                const float* __restrict__ pe,
                                const int*   __restrict__ idx,
                                __nv_bfloat16* __restrict__ xh,
                                __nv_bfloat16* __restrict__ xl)
{
    long i = (long)blockIdx.x * blockDim.x + threadIdx.x;
    const long n4 = (long)MR * HH / 4;
    if (i >= n4) return;
    long row = i / (HH/4);
    long c4  = i - row * (HH/4);
    float4 e = ((const float4*)emb)[i];
    const float4* p = (const float4*)(pe + (long)idx[row]*HH);
    float4 pv = p[c4];
    float v[4] = {e.x+pv.x, e.y+pv.y, e.z+pv.z, e.w+pv.w};
    __nv_bfloat16 h[4], l[4];
    #pragma unroll
    for (int j = 0; j < 4; j++) bsplit(v[j], h[j], l[j]);
    ((__nv_bfloat162*)xh)[2*i]   = __nv_bfloat162(h[0],h[1]);
    ((__nv_bfloat162*)xh)[2*i+1] = __nv_bfloat162(h[2],h[3]);
    ((__nv_bfloat162*)xl)[2*i]   = __nv_bfloat162(l[0],l[1]);
    ((__nv_bfloat162*)xl)[2*i+1] = __nv_bfloat162(l[2],l[3]);
}

__global__ void split_kernel(const float* __restrict__ x,
                             __nv_bfloat16* __restrict__ hi,
                             __nv_bfloat16* __restrict__ lo, long n4)
{
    long i = (long)blockIdx.x * blockDim.x + threadIdx.x;
    if (i >= n4) return;
    float4 v = ((const float4*)x)[i];
    __nv_bfloat16 h[4], l[4];
    bsplit(v.x,h[0],l[0]); bsplit(v.y,h[1],l[1]);
    bsplit(v.z,h[2],l[2]); bsplit(v.w,h[3],l[3]);
    ((__nv_bfloat162*)hi)[2*i]   = __nv_bfloat162(h[0],h[1]);
    ((__nv_bfloat162*)hi)[2*i+1] = __nv_bfloat162(h[2],h[3]);
    ((__nv_bfloat162*)lo)[2*i]   = __nv_bfloat162(l[0],l[1]);
    ((__nv_bfloat162*)lo)[2*i+1] = __nv_bfloat162(l[2],l[3]);
}

// transpose [HH,HH] fp32
__global__ void transpose_k(const float* __restrict__ in, float* __restrict__ out)
{
    __shared__ float t[32][33];
    int x0 = blockIdx.x*32, y0 = blockIdx.y*32;
    int tx = threadIdx.x, ty = threadIdx.y;   // (32,8)
    #pragma unroll
    for (int r = 0; r < 32; r += 8)
        t[ty+r][tx] = in[(long)(y0+ty+r)*HH + x0+tx];
    __syncthreads();
    #pragma unroll
    for (int r = 0; r < 32; r += 8)
        out[(long)(x0+ty+r)*HH + y0+tx] = t[tx][ty+r];
}

// fb[n] = sum_j w[n,j]*bin[j] + badd[n]; one warp per n
__global__ void bias_fold_k(const float* __restrict__ w,
                            const float* __restrict__ bin,
                            const float* __restrict__ badd,
                            float* __restrict__ out)
{
    int n = blockIdx.x * 8 + (threadIdx.x >> 5);
    int lane = threadIdx.x & 31;
    if (n >= HH) return;
    const float* wr = w + (long)n*HH;
    float s = 0.f;
    for (int j = lane; j < HH; j += 32) s += wr[j]*bin[j];
    #pragma unroll
    for (int o = 16; o > 0; o >>= 1) s += __shfl_xor_sync(0xffffffffu, s, o);
    if (lane == 0) out[n] = s + badd[n];
}

__global__ void ln_split_kernel(const float* __restrict__ in,
                                const float* __restrict__ g,
                                const float* __restrict__ b,
                                float* __restrict__ of,
                                __nv_bfloat16* __restrict__ oh,
                                __nv_bfloat16* __restrict__ ol)
{
    __shared__ float sh[8];
    long row = blockIdx.x;
    const float* x = in + row * (long)HH;
    int t = threadIdx.x;
    float v[8];
    float s = 0.f;
    #pragma unroll
    for (int i = 0; i < 8; i++) { v[i] = x[t + i*256]; s += v[i]; }
    #pragma unroll
    for (int o = 16; o > 0; o >>= 1) s += __shfl_xor_sync(0xffffffffu, s, o);
    if ((t & 31) == 0) sh[t >> 5] = s;
    __syncthreads();
    float mean = (sh[0]+sh[1]+sh[2]+sh[3]+sh[4]+sh[5]+sh[6]+sh[7]) * (1.f/HH);
    __syncthreads();
    float sq = 0.f;
    #pragma unroll
    for (int i = 0; i < 8; i++) { float d = v[i]-mean; sq += d*d; }
    #pragma unroll
    for (int o = 16; o > 0; o >>= 1) sq += __shfl_xor_sync(0xffffffffu, sq, o);
    if ((t & 31) == 0) sh[t >> 5] = sq;
    __syncthreads();
    float rstd = rsqrtf((sh[0]+sh[1]+sh[2]+sh[3]+sh[4]+sh[5]+sh[6]+sh[7]) * (1.f/HH) + 1e-5f);
    long base = row * (long)HH;
    #pragma unroll
    for (int i = 0; i < 8; i++) {
        int c = t + i*256;
        float y = (v[i]-mean)*rstd*g[c] + b[c];
        if (of) of[base + c] = y;
        __nv_bfloat16 h, l; bsplit(y, h, l);
        oh[base + c] = h; ol[base + c] = l;
    }
}

__global__ void l2norm_kernel(const float* __restrict__ in, float* __restrict__ out)
{
    __shared__ float sh[8];
    long row = blockIdx.x;
    const float* x = in + row * (long)HH;
    int t = threadIdx.x;
    float v[8];
    float sq = 0.f;
    #pragma unroll
    for (int i = 0; i < 8; i++) { v[i] = x[t + i*256]; sq += v[i]*v[i]; }
    #pragma unroll
    for (int o = 16; o > 0; o >>= 1) sq += __shfl_xor_sync(0xffffffffu, sq, o);
    if ((t & 31) == 0) sh[t >> 5] = sq;
    __syncthreads();
    float tot = sh[0]+sh[1]+sh[2]+sh[3]+sh[4]+sh[5]+sh[6]+sh[7];
    float inv = 1.f / fmaxf(sqrtf(tot), 1e-12f);
    float* orow = out + row * (long)HH;
    #pragma unroll
    for (int i = 0; i < 8; i++) { int c = t + i*256; orow[c] = v[i]*inv; }
}

__global__ void softmax_split(const float* __restrict__ s,
                              __nv_bfloat16* __restrict__ oh,
                              __nv_bfloat16* __restrict__ ol)
{
    long warp = ((long)blockIdx.x * blockDim.x + threadIdx.x) >> 5;
    int lane = threadIdx.x & 31;
    if (warp >= (long)NSROWS) return;
    const float* row = s + warp * (long)SS;
    float vals[16];
    float mx = -1e30f;
    #pragma unroll
    for (int i = 0; i < 16; i++) { vals[i] = row[lane + i*32]; mx = fmaxf(mx, vals[i]); }
    #pragma unroll
    for (int o = 16; o > 0; o >>= 1) mx = fmaxf(mx, __shfl_xor_sync(0xffffffffu, mx, o));
    float sum = 0.f;
    #pragma unroll
    for (int i = 0; i < 16; i++) { vals[i] = __expf(vals[i]-mx); sum += vals[i]; }
    #pragma unroll
    for (int o = 16; o > 0; o >>= 1) sum += __shfl_xor_sync(0xffffffffu, sum, o);
    float inv = 1.f / sum;
    long base = warp * (long)SS;
    #pragma unroll
    for (int i = 0; i < 16; i++) {
        float y = vals[i]*inv;
        __nv_bfloat16 h, l; bsplit(y, h, l);
        oh[base + lane + i*32] = h; ol[base + lane + i*32] = l;
    }
}

__global__ void vtrans_kernel(const __nv_bfloat16* __restrict__ qh,
                              const __nv_bfloat16* __restrict__ ql,
                              __nv_bfloat16* __restrict__ vh,
                              __nv_bfloat16* __restrict__ vl)
{
    __shared__ uint32_t tile[32][33];
    int bh = blockIdx.z;
    int b = bh >> 3, h = bh & 7;
    int s0 = blockIdx.x * 32, d0 = blockIdx.y * 32;
    int tx = threadIdx.x, ty = threadIdx.y;     // (32,8)
    long ibase = (long)b*QSTR + 2*HH + (long)h*HD;
    #pragma unroll
    for (int r = 0; r < 32; r += 8) {
        long idx = ibase + (long)(s0+ty+r)*H3 + d0+tx;
        uint32_t u = ((uint32_t)__bfloat16_as_ushort(qh[idx]) << 16)
                   |  (uint32_t)__bfloat16_as_ushort(ql[idx]);
        tile[ty+r][tx] = u;
    }
    __syncthreads();
    long obase = (long)bh * VTS;
    #pragma unroll
    for (int r = 0; r < 32; r += 8) {
        uint32_t u = tile[tx][ty+r];
        long o = obase + (long)(d0+ty+r)*SS + s0+tx;
        vh[o] = __ushort_as_bfloat16((unsigned short)(u >> 16));
        vl[o] = __ushort_as_bfloat16((unsigned short)(u & 0xffff));
    }
}

// ---------------- mma.sync bf16-split GEMM (R4 2-stage + frag dbuf) ------
#define STG_SZ 65536
#define SM_AH 0
#define SM_AL 16384
#define SM_BH 32768
#define SM_BL 49152
#define SMEMSZ (2*STG_SZ)

template<int ACT, bool RESID, int OMODE>
__global__ void __launch_bounds__(256, 1) tc_gemm(
    const __nv_bfloat16* __restrict__ Ah, const __nv_bfloat16* __restrict__ Al,
    const __nv_bfloat16* __restrict__ Bh, const __nv_bfloat16* __restrict__ Bl,
    const float* __restrict__ bias, const float* __restrict__ Rr,
    float* __restrict__ Cf,
    __nv_bfloat16* __restrict__ Ch, __nv_bfloat16* __restrict__ Cl,
    int K, int lda, int ldb, int ldc,
    long offA1, long offA2, long offB1, long offB2, long offC1, long offC2,
    float alpha)
{
    extern __shared__ char smem[];
    uint32_t sb = (uint32_t)__cvta_generic_to_shared(smem);
    int tid = threadIdx.x;
    int z = blockIdx.z, zb = z >> 3, zh = z & 7;
    long ash = zb*offA1 + zh*offA2;
    long bsh = zb*offB1 + zh*offB2;
    long csh = zb*offC1 + zh*offC2;
    Ah += ash; Al += ash; Bh += bsh; Bl += bsh;
    long m0 = (long)blockIdx.y * 128;
    long n0 = (long)blockIdx.x * 128;

    int l = tid & 31, w = tid >> 5;
    int wm = w & 1, wn = w >> 1;

    uint32_t a_off[4], b_off[2];
    #pragma unroll
    for (int mi = 0; mi < 4; mi++){
        int row = wm*64 + mi*16 + (l & 15);
        a_off[mi] = row*128 + (((l >> 4) << 4) ^ ((row & 7) << 4));
    }
    #pragma unroll
    for (int nj = 0; nj < 2; nj++){
        int row = wn*32 + nj*16 + (l & 7) + ((l & 16) ? 8 : 0);
        b_off[nj] = row*128 + ((((l >> 3) & 1) << 4) ^ ((row & 7) << 4));
    }

    float acc[4][4][4];
    #pragma unroll
    for (int a = 0; a < 4; a++)
        #pragma unroll
        for (int b = 0; b < 4; b++)
            #pragma unroll
            for (int c = 0; c < 4; c++) acc[a][b][c] = 0.f;

    const int NC = K >> 6;
    auto load_chunk = [&](int st, int kc){
        uint32_t base = sb + st*STG_SZ;
        long k0 = (long)kc << 6;
        #pragma unroll
        for (int i = 0; i < 4; i++){
            int task = tid + i*256;
            int row = task >> 3, seg = task & 7;
            uint32_t so = row*128 + ((seg*16) ^ ((row & 7) << 4));
            long ga = (m0 + row) * (long)lda + k0 + seg*8;
            long gb = (n0 + row) * (long)ldb + k0 + seg*8;
            cpa16(base + SM_AH + so, Ah + ga);
            cpa16(base + SM_AL + so, Al + ga);
            cpa16(base + SM_BH + so, Bh + gb);
            cpa16(base + SM_BL + so, Bl + gb);
        }
        asm volatile("cp.async.commit_group;\n" ::: "memory");
    };

    load_chunk(0, 0);
    for (int c = 0; c < NC; c++){
        if (c + 1 < NC){
            load_chunk((c+1)&1, c+1);
            asm volatile("cp.async.wait_group 1;\n" ::: "memory");
        } else {
            asm volatile("cp.async.wait_group 0;\n" ::: "memory");
        }
        __syncthreads();
        uint32_t bAh = sb + (c&1)*STG_SZ + SM_AH;
        uint32_t bAl = sb + (c&1)*STG_SZ + SM_AL;
        uint32_t bBh = sb + (c&1)*STG_SZ + SM_BH;
        uint32_t bBl = sb + (c&1)*STG_SZ + SM_BL;

        // fragment double-buffer across ks
        uint32_t ahf[2][4][4], alf[2][4][4], bhf[2][2][4], blf[2][2][4];
        auto ld_frags = [&](int bf, int ks){
            uint32_t kx = (uint32_t)ks << 5;
            #pragma unroll
            for (int mi = 0; mi < 4; mi++){
                ldsm4(bAh + (a_off[mi] ^ kx), ahf[bf][mi]);
                ldsm4(bAl + (a_off[mi] ^ kx), alf[bf][mi]);
            }
            #pragma unroll
            for (int nj = 0; nj < 2; nj++){
                ldsm4(bBh + (b_off[nj] ^ kx), bhf[bf][nj]);
                ldsm4(bBl + (b_off[nj] ^ kx), blf[bf][nj]);
            }
        };
        ld_frags(0, 0);
        #pragma unroll
        for (int ks = 0; ks < 4; ks++){
            int cur = ks & 1;
            if (ks < 3) ld_frags(cur ^ 1, ks + 1);
            #pragma unroll
            for (int mi = 0; mi < 4; mi++)
                #pragma unroll
                for (int nj = 0; nj < 4; nj++){
                    const uint32_t* b2h = &bhf[cur][nj>>1][(nj&1)*2];
                    const uint32_t* b2l = &blf[cur][nj>>1][(nj&1)*2];
                    mma16816(acc[mi][nj], ahf[cur][mi], b2h);
                    mma16816(acc[mi][nj], alf[cur][mi], b2h);
                    mma16816(acc[mi][nj], ahf[cur][mi], b2l);
                }
        }
        __syncthreads();
    }

    // epilogue
    int r0 = (int)m0 + wm*64 + (l >> 2);
    int c0 = (int)n0 + wn*32 + 2*(l & 3);
    #pragma unroll
    for (int mi = 0; mi < 4; mi++){
        #pragma unroll
        for (int half = 0; half < 2; half++){
            long row = r0 + mi*16 + half*8;
            #pragma unroll
            for (int nj = 0; nj < 4; nj++){
                int cc = c0 + nj*8;
                long o = csh + row*(long)ldc + cc;
                float v0 = acc[mi][nj][half*2+0] * alpha;
                float v1 = acc[mi][nj][half*2+1] * alpha;
                if (bias){ v0 += bias[cc]; v1 += bias[cc+1]; }
                if (ACT == 1){
                    v0 = 0.5f*v0*(1.f + erff(v0*0.70710678118654752f));
                    v1 = 0.5f*v1*(1.f + erff(v1*0.70710678118654752f));
                } else if (ACT == 2){
                    v0 = fmaxf(v0, 0.f); v1 = fmaxf(v1, 0.f);
                }
                if (RESID){
                    const float* rp = Rr + o;
                    v0 += rp[0]; v1 += rp[1];
                }
                if (OMODE == 0){
                    *(float2*)(Cf + o) = make_float2(v0, v1);
                } else {
                    __nv_bfloat16 h0,l0,h1,l1;
                    bsplit(v0,h0,l0); bsplit(v1,h1,l1);
                    *(__nv_bfloat162*)(Ch + o) = __nv_bfloat162(h0,h1);
                    *(__nv_bfloat162*)(Cl + o) = __nv_bfloat162(l0,l1);
                }
            }
        }
    }
}

// ---------------- host orchestration -------------------------------------
extern "C" void kernel_launch(void* const* d_in, const int* in_sizes, int n_in,
                              void* d_out, int out_size)
{
    (void)in_sizes; (void)n_in; (void)out_size;
    const float* emb  = (const float*)d_in[0];
    const int*   tidx = (const int*)  d_in[1];
    const float* pe   = (const float*)d_in[2];
    const float* inw  = (const float*)d_in[3];
    const float* inb  = (const float*)d_in[4];
    const float* ow   = (const float*)d_in[5];
    const float* ob   = (const float*)d_in[6];
    const float* ln1g = (const float*)d_in[7];
    const float* ln1b = (const float*)d_in[8];
    const float* f1w  = (const float*)d_in[9];
    const float* f1b  = (const float*)d_in[10];
    const float* f2w  = (const float*)d_in[11];
    const float* f2b  = (const float*)d_in[12];
    const float* ln2g = (const float*)d_in[13];
    const float* ln2b = (const float*)d_in[14];
    const float* te1w = (const float*)d_in[15];
    const float* te1b = (const float*)d_in[16];
    const float* te2w = (const float*)d_in[17];
    const float* te2b = (const float*)d_in[18];
    const float* pr1w = (const float*)d_in[19];
    const float* pr1b = (const float*)d_in[20];
    const float* pr2w = (const float*)d_in[21];
    const float* pr2b = (const float*)d_in[22];
    float* out = (float*)d_out;

    float *sc,*t1,*t2,*h1,*fb;
    __nv_bfloat16 *pAh,*pAl,*pBh,*pBl,*vh,*vl,*wh,*wl,*fwh,*fwl;
    cudaGetSymbolAddress((void**)&sc,  g_sc);
    cudaGetSymbolAddress((void**)&t1,  g_t1);
    cudaGetSymbolAddress((void**)&t2,  g_t2);
    cudaGetSymbolAddress((void**)&h1,  g_h1);
    cudaGetSymbolAddress((void**)&pAh, g_pAh);
    cudaGetSymbolAddress((void**)&pAl, g_pAl);
    cudaGetSymbolAddress((void**)&pBh, g_pBh);
    cudaGetSymbolAddress((void**)&pBl, g_pBl);
    cudaGetSymbolAddress((void**)&vh,  g_vh);
    cudaGetSymbolAddress((void**)&vl,  g_vl);
    cudaGetSymbolAddress((void**)&wh,  g_wh);
    cudaGetSymbolAddress((void**)&wl,  g_wl);
    cudaGetSymbolAddress((void**)&fwh, g_fwh);
    cudaGetSymbolAddress((void**)&fwl, g_fwl);
    cudaGetSymbolAddress((void**)&fb,  g_fb);

    cudaFuncSetAttribute(tc_gemm<0,false,1>, cudaFuncAttributeMaxDynamicSharedMemorySize, SMEMSZ);
    cudaFuncSetAttribute(tc_gemm<0,false,0>, cudaFuncAttributeMaxDynamicSharedMemorySize, SMEMSZ);
    cudaFuncSetAttribute(tc_gemm<0,true ,0>, cudaFuncAttributeMaxDynamicSharedMemorySize, SMEMSZ);
    cudaFuncSetAttribute(tc_gemm<1,false,1>, cudaFuncAttributeMaxDynamicSharedMemorySize, SMEMSZ);
    cudaFuncSetAttribute(tc_gemm<2,false,1>, cudaFuncAttributeMaxDynamicSharedMemorySize, SMEMSZ);

    auto wsplit = [&](const float* src, long n){
        split_kernel<<<(unsigned)((n/4 + 255) / 256), 256>>>(src, wh, wl, n/4);
    };

    // 0) Fold te2 into pr1: W'' = pr_w1 @ te_w2, b'' = pr_w1@te_b2 + pr_b1.
    //    Uses t1 (fp32 temp), vh/vl and wh/wl (free until steps below).
    transpose_k<<<dim3(64,64), dim3(32,8)>>>(te2w, t1);      // t1 = te_w2^T
    split_kernel<<<(unsigned)(((long)HH*HH/4 + 255)/256), 256>>>(t1, vh, vl, (long)HH*HH/4);
    wsplit(pr1w, (long)HH*HH);
    tc_gemm<0,false,1><<<dim3(HH/128, HH/128, 1), 256, SMEMSZ>>>(
        wh, wl, vh, vl, 0, 0, 0, fwh, fwl,
        HH, HH, HH, HH, 0,0,0,0,0,0, 1.f);
    bias_fold_k<<<HH/8, 256>>>(pr1w, te2b, pr1b, fb);

    // 1) x = emb + pe[idx]  -> poolB
    gather_pe_split<<<(MR*(HH/4) + 255)/256, 256>>>(emb, pe, tidx, pBh, pBl);

    // 2) qkv = x @ in_proj_w^T + b  -> poolA (hi/lo)
    wsplit(inw, (long)H3*HH);
    tc_gemm<0,false,1><<<dim3(H3/128, MR/128, 1), 256, SMEMSZ>>>(
        pBh, pBl, wh, wl, inb, 0, 0, pAh, pAl,
        HH, HH, HH, H3, 0,0,0,0,0,0, 1.f);

    // 3) scores = (Q@K^T)/16 -> fp32 sc   (batched over 256 heads)
    tc_gemm<0,false,0><<<dim3(SS/128, SS/128, NHEADS), 256, SMEMSZ>>>(
        pAh, pAl, pAh + HH, pAl + HH, 0, 0, sc, 0, 0,
        HD, H3, H3, SS, QSTR, HD, QSTR, HD, 8*SCH, SCH, 0.0625f);

    // 4) Vt transpose (from qkv hi/lo), softmax -> poolB
    vtrans_kernel<<<dim3(SS/32, HD/32, NHEADS), dim3(32,8)>>>(pAh, pAl, vh, vl);
    softmax_split<<<NSROWS/8, 256>>>(sc, pBh, pBl);

    // 5) o = A @ V -> poolA (hi/lo)
    tc_gemm<0,false,1><<<dim3(HD/128, SS/128, NHEADS), 256, SMEMSZ>>>(
        pBh, pBl, vh, vl, 0, 0, 0, pAh, pAl,
        SS, SS, SS, HH, 8*SCH, SCH, 8*VTS, VTS, (long)SS*HH, HD, 1.f);

    // 6) t1 = o @ out_proj_w^T + b + emb -> fp32
    wsplit(ow, (long)HH*HH);
    tc_gemm<0,true,0><<<dim3(HH/128, MR/128, 1), 256, SMEMSZ>>>(
        pAh, pAl, wh, wl, ob, emb, t1, 0, 0,
        HH, HH, HH, HH, 0,0,0,0,0,0, 1.f);

    // 7) h1 = LN(t1) -> fp32 (residual) + poolB (hi/lo)
    ln_split_kernel<<<MR, 256>>>(t1, ln1g, ln1b, h1, pBh, pBl);

    // 8) mid = gelu(h1 @ ffn_w1^T + b1) -> poolA (hi/lo)
    wsplit(f1w, (long)H4*HH);
    tc_gemm<1,false,1><<<dim3(H4/128, MR/128, 1), 256, SMEMSZ>>>(
        pBh, pBl, wh, wl, f1b, 0, 0, pAh, pAl,
        HH, HH, HH, H4, 0,0,0,0,0,0, 1.f);

    // 9) t2 = mid @ ffn_w2^T + b2 + h1 -> fp32
    wsplit(f2w, (long)HH*H4);
    tc_gemm<0,true,0><<<dim3(HH/128, MR/128, 1), 256, SMEMSZ>>>(
        pAh, pAl, wh, wl, f2b, h1, t2, 0, 0,
        H4, H4, H4, HH, 0,0,0,0,0,0, 1.f);

    // 10) h2 = LN(t2) -> poolB (hi/lo only)
    ln_split_kernel<<<MR, 256>>>(t2, ln2g, ln2b, 0, pBh, pBl);

    // 11) r1 = relu(h2 @ te_w1^T + b1) -> poolA
    wsplit(te1w, (long)HH*HH);
    tc_gemm<2,false,1><<<dim3(HH/128, MR/128, 1), 256, SMEMSZ>>>(
        pBh, pBl, wh, wl, te1b, 0, 0, pAh, pAl,
        HH, HH, HH, HH, 0,0,0,0,0,0, 1.f);

    // 12) r2 = relu(r1 @ W''^T + b'')  [te2+pr1 folded] -> poolB
    tc_gemm<2,false,1><<<dim3(HH/128, MR/128, 1), 256, SMEMSZ>>>(
        pAh, pAl, fwh, fwl, fb, 0, 0, pBh, pBl,
        HH, HH, HH, HH, 0,0,0,0,0,0, 1.f);

    // 13) pr2 -> fp32 t1
    wsplit(pr2w, (long)HH*HH);
    tc_gemm<0,false,0><<<dim3(HH/128, MR/128, 1), 256, SMEMSZ>>>(
        pBh, pBl, wh, wl, pr2b, 0, t1, 0, 0,
        HH, HH, HH, HH, 0,0,0,0,0,0, 1.f);

    // 14) out = pr / max(||pr||, 1e-12)
    l2norm_kernel<<<MR, 256>>>(t1, out);
}

// round 7
// speedup vs baseline: 1.1211x; 1.0390x over previous
#include <cuda_runtime.h>
#include <cuda_bf16.h>
#include <math.h>
#include <stdint.h>

#define BB 32
#define SS 512
#define HH 2048
#define NHH 8
#define HD 256
#define MR (BB*SS)           // 16384
#define H3 (3*HH)            // 6144
#define H4 (4*HH)            // 8192
#define NHEADS (BB*NHH)      // 256
#define NSROWS (NHEADS*SS)
#define SCH ((long)SS*SS)
#define QSTR ((long)SS*H3)
#define VTS ((long)HD*SS)

// ---------------- scratch (device globals) ------------------------------
__device__ __align__(16) float g_sc [(size_t)NHEADS*SS*SS];   // fp32 scores
__device__ __align__(16) float g_t1 [(size_t)MR*HH];
__device__ __align__(16) float g_t2 [(size_t)MR*HH];
__device__ __align__(16) float g_h1 [(size_t)MR*HH];
// bf16 hi/lo pools
__device__ __align__(16) __nv_bfloat16 g_pAh[(size_t)MR*H4];
__device__ __align__(16) __nv_bfloat16 g_pAl[(size_t)MR*H4];
__device__ __align__(16) __nv_bfloat16 g_pBh[(size_t)NHEADS*SS*SS];
__device__ __align__(16) __nv_bfloat16 g_pBl[(size_t)NHEADS*SS*SS];
__device__ __align__(16) __nv_bfloat16 g_vh [(size_t)MR*HH];
__device__ __align__(16) __nv_bfloat16 g_vl [(size_t)MR*HH];
__device__ __align__(16) __nv_bfloat16 g_wh [(size_t)H4*HH];
__device__ __align__(16) __nv_bfloat16 g_wl [(size_t)H4*HH];
// folded te2*pr1 weight + bias
__device__ __align__(16) __nv_bfloat16 g_fwh[(size_t)HH*HH];
__device__ __align__(16) __nv_bfloat16 g_fwl[(size_t)HH*HH];
__device__ __align__(16) float g_fb[HH];

// ---------------- helpers ------------------------------------------------
__device__ __forceinline__ void bsplit(float v, __nv_bfloat16& h, __nv_bfloat16& l){
    h = __float2bfloat16(v);
    l = __float2bfloat16(v - __bfloat162float(h));
}
__device__ __forceinline__ void cpa16(uint32_t s, const void* g){
    asm volatile("cp.async.cg.shared.global [%0], [%1], 16;\n" :: "r"(s), "l"(g));
}
__device__ __forceinline__ void ldsm4(uint32_t addr, uint32_t* r){
    asm volatile("ldmatrix.sync.aligned.m8n8.x4.shared.b16 {%0,%1,%2,%3}, [%4];\n"
        : "=r"(r[0]),"=r"(r[1]),"=r"(r[2]),"=r"(r[3]) : "r"(addr));
}
__device__ __forceinline__ void mma16816(float* d, const uint32_t* a, const uint32_t* b){
    asm volatile("mma.sync.aligned.m16n8k16.row.col.f32.bf16.bf16.f32 "
        "{%0,%1,%2,%3}, {%4,%5,%6,%7}, {%8,%9}, {%0,%1,%2,%3};\n"
        : "+f"(d[0]),"+f"(d[1]),"+f"(d[2]),"+f"(d[3])
        : "r"(a[0]),"r"(a[1]),"r"(a[2]),"r"(a[3]), "r"(b[0]),"r"(b[1]));
}

// ---------------- elementwise kernels ------------------------------------
__global__ void gather_pe_split(const float* __restrict__ emb,
                                const float* __restrict__ pe,
                                const int*   __restrict__ idx,
                                __nv_bfloat16* __restrict__ xh,
                                __nv_bfloat16* __restrict__ xl)
{
    long i = (long)blockIdx.x * blockDim.x + threadIdx.x;
    const long n4 = (long)MR * HH / 4;
    if (i >= n4) return;
    long row = i / (HH/4);
    long c4  = i - row * (HH/4);
    float4 e = ((const float4*)emb)[i];
    const float4* p = (const float4*)(pe + (long)idx[row]*HH);
    float4 pv = p[c4];
    float v[4] = {e.x+pv.x, e.y+pv.y, e.z+pv.z, e.w+pv.w};
    __nv_bfloat16 h[4], l[4];
    #pragma unroll
    for (int j = 0; j < 4; j++) bsplit(v[j], h[j], l[j]);
    ((__nv_bfloat162*)xh)[2*i]   = __nv_bfloat162(h[0],h[1]);
    ((__nv_bfloat162*)xh)[2*i+1] = __nv_bfloat162(h[2],h[3]);
    ((__nv_bfloat162*)xl)[2*i]   = __nv_bfloat162(l[0],l[1]);
    ((__nv_bfloat162*)xl)[2*i+1] = __nv_bfloat162(l[2],l[3]);
}

__global__ void split_kernel(const float* __restrict__ x,
                             __nv_bfloat16* __restrict__ hi,
                             __nv_bfloat16* __restrict__ lo, long n4)
{
    long i = (long)blockIdx.x * blockDim.x + threadIdx.x;
    if (i >= n4) return;
    float4 v = ((const float4*)x)[i];
    __nv_bfloat16 h[4], l[4];
    bsplit(v.x,h[0],l[0]); bsplit(v.y,h[1],l[1]);
    bsplit(v.z,h[2],l[2]); bsplit(v.w,h[3],l[3]);
    ((__nv_bfloat162*)hi)[2*i]   = __nv_bfloat162(h[0],h[1]);
    ((__nv_bfloat162*)hi)[2*i+1] = __nv_bfloat162(h[2],h[3]);
    ((__nv_bfloat162*)lo)[2*i]   = __nv_bfloat162(l[0],l[1]);
    ((__nv_bfloat162*)lo)[2*i+1] = __nv_bfloat162(l[2],l[3]);
}

// transpose [HH,HH] fp32
__global__ void transpose_k(const float* __restrict__ in, float* __restrict__ out)
{
    __shared__ float t[32][33];
    int x0 = blockIdx.x*32, y0 = blockIdx.y*32;
    int tx = threadIdx.x, ty = threadIdx.y;   // (32,8)
    #pragma unroll
    for (int r = 0; r < 32; r += 8)
        t[ty+r][tx] = in[(long)(y0+ty+r)*HH + x0+tx];
    __syncthreads();
    #pragma unroll
    for (int r = 0; r < 32; r += 8)
        out[(long)(x0+ty+r)*HH + y0+tx] = t[tx][ty+r];
}

__global__ void bias_fold_k(const float* __restrict__ w,
                            const float* __restrict__ bin,
                            const float* __restrict__ badd,
                            float* __restrict__ out)
{
    int n = blockIdx.x * 8 + (threadIdx.x >> 5);
    int lane = threadIdx.x & 31;
    if (n >= HH) return;
    const float* wr = w + (long)n*HH;
    float s = 0.f;
    for (int j = lane; j < HH; j += 32) s += wr[j]*bin[j];
    #pragma unroll
    for (int o = 16; o > 0; o >>= 1) s += __shfl_xor_sync(0xffffffffu, s, o);
    if (lane == 0) out[n] = s + badd[n];
}

__global__ void ln_split_kernel(const float* __restrict__ in,
                                const float* __restrict__ g,
                                const float* __restrict__ b,
                                float* __restrict__ of,
                                __nv_bfloat16* __restrict__ oh,
                                __nv_bfloat16* __restrict__ ol)
{
    __shared__ float sh[8];
    long row = blockIdx.x;
    const float* x = in + row * (long)HH;
    int t = threadIdx.x;
    float v[8];
    float s = 0.f;
    #pragma unroll
    for (int i = 0; i < 8; i++) { v[i] = x[t + i*256]; s += v[i]; }
    #pragma unroll
    for (int o = 16; o > 0; o >>= 1) s += __shfl_xor_sync(0xffffffffu, s, o);
    if ((t & 31) == 0) sh[t >> 5] = s;
    __syncthreads();
    float mean = (sh[0]+sh[1]+sh[2]+sh[3]+sh[4]+sh[5]+sh[6]+sh[7]) * (1.f/HH);
    __syncthreads();
    float sq = 0.f;
    #pragma unroll
    for (int i = 0; i < 8; i++) { float d = v[i]-mean; sq += d*d; }
    #pragma unroll
    for (int o = 16; o > 0; o >>= 1) sq += __shfl_xor_sync(0xffffffffu, sq, o);
    if ((t & 31) == 0) sh[t >> 5] = sq;
    __syncthreads();
    float rstd = rsqrtf((sh[0]+sh[1]+sh[2]+sh[3]+sh[4]+sh[5]+sh[6]+sh[7]) * (1.f/HH) + 1e-5f);
    long base = row * (long)HH;
    #pragma unroll
    for (int i = 0; i < 8; i++) {
        int c = t + i*256;
        float y = (v[i]-mean)*rstd*g[c] + b[c];
        if (of) of[base + c] = y;
        __nv_bfloat16 h, l; bsplit(y, h, l);
        oh[base + c] = h; ol[base + c] = l;
    }
}

__global__ void l2norm_kernel(const float* __restrict__ in, float* __restrict__ out)
{
    __shared__ float sh[8];
    long row = blockIdx.x;
    const float* x = in + row * (long)HH;
    int t = threadIdx.x;
    float v[8];
    float sq = 0.f;
    #pragma unroll
    for (int i = 0; i < 8; i++) { v[i] = x[t + i*256]; sq += v[i]*v[i]; }
    #pragma unroll
    for (int o = 16; o > 0; o >>= 1) sq += __shfl_xor_sync(0xffffffffu, sq, o);
    if ((t & 31) == 0) sh[t >> 5] = sq;
    __syncthreads();
    float tot = sh[0]+sh[1]+sh[2]+sh[3]+sh[4]+sh[5]+sh[6]+sh[7];
    float inv = 1.f / fmaxf(sqrtf(tot), 1e-12f);
    float* orow = out + row * (long)HH;
    #pragma unroll
    for (int i = 0; i < 8; i++) { int c = t + i*256; orow[c] = v[i]*inv; }
}

__global__ void softmax_split(const float* __restrict__ s,
                              __nv_bfloat16* __restrict__ oh,
                              __nv_bfloat16* __restrict__ ol)
{
    long warp = ((long)blockIdx.x * blockDim.x + threadIdx.x) >> 5;
    int lane = threadIdx.x & 31;
    if (warp >= (long)NSROWS) return;
    const float* row = s + warp * (long)SS;
    float vals[16];
    float mx = -1e30f;
    #pragma unroll
    for (int i = 0; i < 16; i++) { vals[i] = row[lane + i*32]; mx = fmaxf(mx, vals[i]); }
    #pragma unroll
    for (int o = 16; o > 0; o >>= 1) mx = fmaxf(mx, __shfl_xor_sync(0xffffffffu, mx, o));
    float sum = 0.f;
    #pragma unroll
    for (int i = 0; i < 16; i++) { vals[i] = __expf(vals[i]-mx); sum += vals[i]; }
    #pragma unroll
    for (int o = 16; o > 0; o >>= 1) sum += __shfl_xor_sync(0xffffffffu, sum, o);
    float inv = 1.f / sum;
    long base = warp * (long)SS;
    #pragma unroll
    for (int i = 0; i < 16; i++) {
        float y = vals[i]*inv;
        __nv_bfloat16 h, l; bsplit(y, h, l);
        oh[base + lane + i*32] = h; ol[base + lane + i*32] = l;
    }
}

__global__ void vtrans_kernel(const __nv_bfloat16* __restrict__ qh,
                              const __nv_bfloat16* __restrict__ ql,
                              __nv_bfloat16* __restrict__ vh,
                              __nv_bfloat16* __restrict__ vl)
{
    __shared__ uint32_t tile[32][33];
    int bh = blockIdx.z;
    int b = bh >> 3, h = bh & 7;
    int s0 = blockIdx.x * 32, d0 = blockIdx.y * 32;
    int tx = threadIdx.x, ty = threadIdx.y;     // (32,8)
    long ibase = (long)b*QSTR + 2*HH + (long)h*HD;
    #pragma unroll
    for (int r = 0; r < 32; r += 8) {
        long idx = ibase + (long)(s0+ty+r)*H3 + d0+tx;
        uint32_t u = ((uint32_t)__bfloat16_as_ushort(qh[idx]) << 16)
                   |  (uint32_t)__bfloat16_as_ushort(ql[idx]);
        tile[ty+r][tx] = u;
    }
    __syncthreads();
    long obase = (long)bh * VTS;
    #pragma unroll
    for (int r = 0; r < 32; r += 8) {
        uint32_t u = tile[tx][ty+r];
        long o = obase + (long)(d0+ty+r)*SS + s0+tx;
        vh[o] = __ushort_as_bfloat16((unsigned short)(u >> 16));
        vl[o] = __ushort_as_bfloat16((unsigned short)(u & 0xffff));
    }
}

// ---------------- mma.sync bf16-split GEMM, 128x256 CTA tile -------------
// 8 warps of 64x64. 2-stage cp.async. K chunk 64.
#define STG_SZ 98304
#define SM_AH 0
#define SM_AL 16384
#define SM_BH 32768
#define SM_BL 65536
#define SMEMSZ (2*STG_SZ)

template<int ACT, bool RESID, int OMODE>
__global__ void __launch_bounds__(256, 1) tc_gemm(
    const __nv_bfloat16* __restrict__ Ah, const __nv_bfloat16* __restrict__ Al,
    const __nv_bfloat16* __restrict__ Bh, const __nv_bfloat16* __restrict__ Bl,
    const float* __restrict__ bias, const float* __restrict__ Rr,
    float* __restrict__ Cf,
    __nv_bfloat16* __restrict__ Ch, __nv_bfloat16* __restrict__ Cl,
    int K, int lda, int ldb, int ldc,
    long offA1, long offA2, long offB1, long offB2, long offC1, long offC2,
    float alpha)
{
    extern __shared__ char smem[];
    uint32_t sb = (uint32_t)__cvta_generic_to_shared(smem);
    int tid = threadIdx.x;
    int z = blockIdx.z, zb = z >> 3, zh = z & 7;
    long ash = zb*offA1 + zh*offA2;
    long bsh = zb*offB1 + zh*offB2;
    long csh = zb*offC1 + zh*offC2;
    Ah += ash; Al += ash; Bh += bsh; Bl += bsh;
    long m0 = (long)blockIdx.y * 128;
    long n0 = (long)blockIdx.x * 256;

    int l = tid & 31, w = tid >> 5;
    int wm = w & 1, wn = w >> 1;        // 2 x 4 warps, each 64x64

    uint32_t a_off[4], b_off[4];
    #pragma unroll
    for (int mi = 0; mi < 4; mi++){
        int row = wm*64 + mi*16 + (l & 15);
        a_off[mi] = row*128 + (((l >> 4) << 4) ^ ((row & 7) << 4));
    }
    #pragma unroll
    for (int nj = 0; nj < 4; nj++){
        int row = wn*64 + nj*16 + (l & 7) + ((l & 16) ? 8 : 0);
        b_off[nj] = row*128 + ((((l >> 3) & 1) << 4) ^ ((row & 7) << 4));
    }

    float acc[4][8][4];
    #pragma unroll
    for (int a = 0; a < 4; a++)
        #pragma unroll
        for (int b = 0; b < 8; b++)
            #pragma unroll
            for (int c = 0; c < 4; c++) acc[a][b][c] = 0.f;

    const int NC = K >> 6;
    auto load_chunk = [&](int st, int kc){
        uint32_t base = sb + st*STG_SZ;
        long k0 = (long)kc << 6;
        #pragma unroll
        for (int i = 0; i < 4; i++){             // A: 1024 tasks
            int task = tid + i*256;
            int row = task >> 3, seg = task & 7;
            uint32_t so = row*128 + ((seg*16) ^ ((row & 7) << 4));
            long ga = (m0 + row) * (long)lda + k0 + seg*8;
            cpa16(base + SM_AH + so, Ah + ga);
            cpa16(base + SM_AL + so, Al + ga);
        }
        #pragma unroll
        for (int i = 0; i < 8; i++){             // B: 2048 tasks
            int task = tid + i*256;
            int row = task >> 3, seg = task & 7;
            uint32_t so = row*128 + ((seg*16) ^ ((row & 7) << 4));
            long gb = (n0 + row) * (long)ldb + k0 + seg*8;
            cpa16(base + SM_BH + so, Bh + gb);
            cpa16(base + SM_BL + so, Bl + gb);
        }
        asm volatile("cp.async.commit_group;\n" ::: "memory");
    };

    load_chunk(0, 0);
    for (int c = 0; c < NC; c++){
        if (c + 1 < NC){
            load_chunk((c+1)&1, c+1);
            asm volatile("cp.async.wait_group 1;\n" ::: "memory");
        } else {
            asm volatile("cp.async.wait_group 0;\n" ::: "memory");
        }
        __syncthreads();
        uint32_t bAh = sb + (c&1)*STG_SZ + SM_AH;
        uint32_t bAl = sb + (c&1)*STG_SZ + SM_AL;
        uint32_t bBh = sb + (c&1)*STG_SZ + SM_BH;
        uint32_t bBl = sb + (c&1)*STG_SZ + SM_BL;
        #pragma unroll
        for (int ks = 0; ks < 4; ks++){
            uint32_t kx = (uint32_t)ks << 5;
            uint32_t ahf[4][4], alf[4][4], bhf[4][4], blf[4][4];
            #pragma unroll
            for (int mi = 0; mi < 4; mi++){
                ldsm4(bAh + (a_off[mi] ^ kx), ahf[mi]);
                ldsm4(bAl + (a_off[mi] ^ kx), alf[mi]);
            }
            #pragma unroll
            for (int nj = 0; nj < 4; nj++){
                ldsm4(bBh + (b_off[nj] ^ kx), bhf[nj]);
                ldsm4(bBl + (b_off[nj] ^ kx), blf[nj]);
            }
            #pragma unroll
            for (int mi = 0; mi < 4; mi++)
                #pragma unroll
                for (int nj = 0; nj < 8; nj++){
                    const uint32_t* b2h = &bhf[nj>>1][(nj&1)*2];
                    const uint32_t* b2l = &blf[nj>>1][(nj&1)*2];
                    mma16816(acc[mi][nj], ahf[mi], b2h);
                    mma16816(acc[mi][nj], alf[mi], b2h);
                    mma16816(acc[mi][nj], ahf[mi], b2l);
                }
        }
        __syncthreads();
    }

    // epilogue
    int r0 = (int)m0 + wm*64 + (l >> 2);
    int c0 = (int)n0 + wn*64 + 2*(l & 3);
    #pragma unroll
    for (int mi = 0; mi < 4; mi++){
        #pragma unroll
        for (int half = 0; half < 2; half++){
            long row = r0 + mi*16 + half*8;
            #pragma unroll
            for (int nj = 0; nj < 8; nj++){
                int cc = c0 + nj*8;
                long o = csh + row*(long)ldc + cc;
                float v0 = acc[mi][nj][half*2+0] * alpha;
                float v1 = acc[mi][nj][half*2+1] * alpha;
                if (bias){ v0 += bias[cc]; v1 += bias[cc+1]; }
                if (ACT == 1){
                    v0 = 0.5f*v0*(1.f + erff(v0*0.70710678118654752f));
                    v1 = 0.5f*v1*(1.f + erff(v1*0.70710678118654752f));
                } else if (ACT == 2){
                    v0 = fmaxf(v0, 0.f); v1 = fmaxf(v1, 0.f);
                }
                if (RESID){
                    const float* rp = Rr + o;
                    v0 += rp[0]; v1 += rp[1];
                }
                if (OMODE == 0){
                    *(float2*)(Cf + o) = make_float2(v0, v1);
                } else {
                    __nv_bfloat16 h0,l0,h1,l1;
                    bsplit(v0,h0,l0); bsplit(v1,h1,l1);
                    *(__nv_bfloat162*)(Ch + o) = __nv_bfloat162(h0,h1);
                    *(__nv_bfloat162*)(Cl + o) = __nv_bfloat162(l0,l1);
                }
            }
        }
    }
}

// ---------------- host orchestration -------------------------------------
extern "C" void kernel_launch(void* const* d_in, const int* in_sizes, int n_in,
                              void* d_out, int out_size)
{
    (void)in_sizes; (void)n_in; (void)out_size;
    const float* emb  = (const float*)d_in[0];
    const int*   tidx = (const int*)  d_in[1];
    const float* pe   = (const float*)d_in[2];
    const float* inw  = (const float*)d_in[3];
    const float* inb  = (const float*)d_in[4];
    const float* ow   = (const float*)d_in[5];
    const float* ob   = (const float*)d_in[6];
    const float* ln1g = (const float*)d_in[7];
    const float* ln1b = (const float*)d_in[8];
    const float* f1w  = (const float*)d_in[9];
    const float* f1b  = (const float*)d_in[10];
    const float* f2w  = (const float*)d_in[11];
    const float* f2b  = (const float*)d_in[12];
    const float* ln2g = (const float*)d_in[13];
    const float* ln2b = (const float*)d_in[14];
    const float* te1w = (const float*)d_in[15];
    const float* te1b = (const float*)d_in[16];
    const float* te2w = (const float*)d_in[17];
    const float* te2b = (const float*)d_in[18];
    const float* pr1w = (const float*)d_in[19];
    const float* pr1b = (const float*)d_in[20];
    const float* pr2w = (const float*)d_in[21];
    const float* pr2b = (const float*)d_in[22];
    float* out = (float*)d_out;

    float *sc,*t1,*t2,*h1,*fb;
    __nv_bfloat16 *pAh,*pAl,*pBh,*pBl,*vh,*vl,*wh,*wl,*fwh,*fwl;
    cudaGetSymbolAddress((void**)&sc,  g_sc);
    cudaGetSymbolAddress((void**)&t1,  g_t1);
    cudaGetSymbolAddress((void**)&t2,  g_t2);
    cudaGetSymbolAddress((void**)&h1,  g_h1);
    cudaGetSymbolAddress((void**)&pAh, g_pAh);
    cudaGetSymbolAddress((void**)&pAl, g_pAl);
    cudaGetSymbolAddress((void**)&pBh, g_pBh);
    cudaGetSymbolAddress((void**)&pBl, g_pBl);
    cudaGetSymbolAddress((void**)&vh,  g_vh);
    cudaGetSymbolAddress((void**)&vl,  g_vl);
    cudaGetSymbolAddress((void**)&wh,  g_wh);
    cudaGetSymbolAddress((void**)&wl,  g_wl);
    cudaGetSymbolAddress((void**)&fwh, g_fwh);
    cudaGetSymbolAddress((void**)&fwl, g_fwl);
    cudaGetSymbolAddress((void**)&fb,  g_fb);

    cudaFuncSetAttribute(tc_gemm<0,false,1>, cudaFuncAttributeMaxDynamicSharedMemorySize, SMEMSZ);
    cudaFuncSetAttribute(tc_gemm<0,false,0>, cudaFuncAttributeMaxDynamicSharedMemorySize, SMEMSZ);
    cudaFuncSetAttribute(tc_gemm<0,true ,0>, cudaFuncAttributeMaxDynamicSharedMemorySize, SMEMSZ);
    cudaFuncSetAttribute(tc_gemm<1,false,1>, cudaFuncAttributeMaxDynamicSharedMemorySize, SMEMSZ);
    cudaFuncSetAttribute(tc_gemm<2,false,1>, cudaFuncAttributeMaxDynamicSharedMemorySize, SMEMSZ);

    auto wsplit = [&](const float* src, long n){
        split_kernel<<<(unsigned)((n/4 + 255) / 256), 256>>>(src, wh, wl, n/4);
    };

    // 0) Fold te2 into pr1: W'' = pr_w1 @ te_w2, b'' = pr_w1@te_b2 + pr_b1
    transpose_k<<<dim3(64,64), dim3(32,8)>>>(te2w, t1);      // t1 = te_w2^T
    split_kernel<<<(unsigned)(((long)HH*HH/4 + 255)/256), 256>>>(t1, vh, vl, (long)HH*HH/4);
    wsplit(pr1w, (long)HH*HH);
    tc_gemm<0,false,1><<<dim3(HH/256, HH/128, 1), 256, SMEMSZ>>>(
        wh, wl, vh, vl, 0, 0, 0, fwh, fwl,
        HH, HH, HH, HH, 0,0,0,0,0,0, 1.f);
    bias_fold_k<<<HH/8, 256>>>(pr1w, te2b, pr1b, fb);

    // 1) x = emb + pe[idx]  -> poolB
    gather_pe_split<<<(MR*(HH/4) + 255)/256, 256>>>(emb, pe, tidx, pBh, pBl);

    // 2) qkv = x @ in_proj_w^T + b  -> poolA (hi/lo)
    wsplit(inw, (long)H3*HH);
    tc_gemm<0,false,1><<<dim3(H3/256, MR/128, 1), 256, SMEMSZ>>>(
        pBh, pBl, wh, wl, inb, 0, 0, pAh, pAl,
        HH, HH, HH, H3, 0,0,0,0,0,0, 1.f);

    // 3) scores = (Q@K^T)/16 -> fp32 sc   (batched over 256 heads)
    tc_gemm<0,false,0><<<dim3(SS/256, SS/128, NHEADS), 256, SMEMSZ>>>(
        pAh, pAl, pAh + HH, pAl + HH, 0, 0, sc, 0, 0,
        HD, H3, H3, SS, QSTR, HD, QSTR, HD, 8*SCH, SCH, 0.0625f);

    // 4) Vt transpose (from qkv hi/lo), softmax -> poolB
    vtrans_kernel<<<dim3(SS/32, HD/32, NHEADS), dim3(32,8)>>>(pAh, pAl, vh, vl);
    softmax_split<<<NSROWS/8, 256>>>(sc, pBh, pBl);

    // 5) o = A @ V -> poolA (hi/lo)
    tc_gemm<0,false,1><<<dim3(HD/256, SS/128, NHEADS), 256, SMEMSZ>>>(
        pBh, pBl, vh, vl, 0, 0, 0, pAh, pAl,
        SS, SS, SS, HH, 8*SCH, SCH, 8*VTS, VTS, (long)SS*HH, HD, 1.f);

    // 6) t1 = o @ out_proj_w^T + b + emb -> fp32
    wsplit(ow, (long)HH*HH);
    tc_gemm<0,true,0><<<dim3(HH/256, MR/128, 1), 256, SMEMSZ>>>(
        pAh, pAl, wh, wl, ob, emb, t1, 0, 0,
        HH, HH, HH, HH, 0,0,0,0,0,0, 1.f);

    // 7) h1 = LN(t1) -> fp32 (residual) + poolB (hi/lo)
    ln_split_kernel<<<MR, 256>>>(t1, ln1g, ln1b, h1, pBh, pBl);

    // 8) mid = gelu(h1 @ ffn_w1^T + b1) -> poolA (hi/lo)
    wsplit(f1w, (long)H4*HH);
    tc_gemm<1,false,1><<<dim3(H4/256, MR/128, 1), 256, SMEMSZ>>>(
        pBh, pBl, wh, wl, f1b, 0, 0, pAh, pAl,
        HH, HH, HH, H4, 0,0,0,0,0,0, 1.f);

    // 9) t2 = mid @ ffn_w2^T + b2 + h1 -> fp32
    wsplit(f2w, (long)HH*H4);
    tc_gemm<0,true,0><<<dim3(HH/256, MR/128, 1), 256, SMEMSZ>>>(
        pAh, pAl, wh, wl, f2b, h1, t2, 0, 0,
        H4, H4, H4, HH, 0,0,0,0,0,0, 1.f);

    // 10) h2 = LN(t2) -> poolB (hi/lo only)
    ln_split_kernel<<<MR, 256>>>(t2, ln2g, ln2b, 0, pBh, pBl);

    // 11) r1 = relu(h2 @ te_w1^T + b1) -> poolA
    wsplit(te1w, (long)HH*HH);
    tc_gemm<2,false,1><<<dim3(HH/256, MR/128, 1), 256, SMEMSZ>>>(
        pBh, pBl, wh, wl, te1b, 0, 0, pAh, pAl,
        HH, HH, HH, HH, 0,0,0,0,0,0, 1.f);

    // 12) r2 = relu(r1 @ W''^T + b'')  [te2+pr1 folded] -> poolB
    tc_gemm<2,false,1><<<dim3(HH/256, MR/128, 1), 256, SMEMSZ>>>(
        pAh, pAl, fwh, fwl, fb, 0, 0, pBh, pBl,
        HH, HH, HH, HH, 0,0,0,0,0,0, 1.f);

    // 13) pr2 -> fp32 t1
    wsplit(pr2w, (long)HH*HH);
    tc_gemm<0,false,0><<<dim3(HH/256, MR/128, 1), 256, SMEMSZ>>>(
        pBh, pBl, wh, wl, pr2b, 0, t1, 0, 0,
        HH, HH, HH, HH, 0,0,0,0,0,0, 1.f);

    // 14) out = pr / max(||pr||, 1e-12)
    l2norm_kernel<<<MR, 256>>>(t1, out);
}

// round 8
// speedup vs baseline: 1.1370x; 1.0141x over previous
#include <cuda_runtime.h>
#include <cuda_bf16.h>
#include <math.h>
#include <stdint.h>

#define BB 32
#define SS 512
#define HH 2048
#define NHH 8
#define HD 256
#define MR (BB*SS)           // 16384
#define H3 (3*HH)            // 6144
#define H4 (4*HH)            // 8192
#define NHEADS (BB*NHH)      // 256
#define NSROWS (NHEADS*SS)
#define SCH ((long)SS*SS)
#define QSTR ((long)SS*H3)
#define VTS ((long)HD*SS)

// ---------------- scratch (device globals) ------------------------------
__device__ __align__(16) float g_sc [(size_t)NHEADS*SS*SS];   // fp32 scores
__device__ __align__(16) float g_t1 [(size_t)MR*HH];
__device__ __align__(16) float g_t2 [(size_t)MR*HH];
__device__ __align__(16) float g_h1 [(size_t)MR*HH];
// bf16 hi/lo pools
__device__ __align__(16) __nv_bfloat16 g_pAh[(size_t)MR*H4];
__device__ __align__(16) __nv_bfloat16 g_pAl[(size_t)MR*H4];
__device__ __align__(16) __nv_bfloat16 g_pBh[(size_t)NHEADS*SS*SS];
__device__ __align__(16) __nv_bfloat16 g_pBl[(size_t)NHEADS*SS*SS];
__device__ __align__(16) __nv_bfloat16 g_vh [(size_t)MR*HH];
__device__ __align__(16) __nv_bfloat16 g_vl [(size_t)MR*HH];
__device__ __align__(16) __nv_bfloat16 g_wh [(size_t)H4*HH];
__device__ __align__(16) __nv_bfloat16 g_wl [(size_t)H4*HH];
// folded te2*pr1 weight + bias
__device__ __align__(16) __nv_bfloat16 g_fwh[(size_t)HH*HH];
__device__ __align__(16) __nv_bfloat16 g_fwl[(size_t)HH*HH];
__device__ __align__(16) float g_fb[HH];

// ---------------- helpers ------------------------------------------------
__device__ __forceinline__ void bsplit(float v, __nv_bfloat16& h, __nv_bfloat16& l){
    h = __float2bfloat16(v);
    l = __float2bfloat16(v - __bfloat162float(h));
}
__device__ __forceinline__ void cpa16(uint32_t s, const void* g){
    asm volatile("cp.async.cg.shared.global [%0], [%1], 16;\n" :: "r"(s), "l"(g));
}
__device__ __forceinline__ void ldsm4(uint32_t addr, uint32_t* r){
    asm volatile("ldmatrix.sync.aligned.m8n8.x4.shared.b16 {%0,%1,%2,%3}, [%4];\n"
        : "=r"(r[0]),"=r"(r[1]),"=r"(r[2]),"=r"(r[3]) : "r"(addr));
}
__device__ __forceinline__ void mma16816(float* d, const uint32_t* a, const uint32_t* b){
    asm volatile("mma.sync.aligned.m16n8k16.row.col.f32.bf16.bf16.f32 "
        "{%0,%1,%2,%3}, {%4,%5,%6,%7}, {%8,%9}, {%0,%1,%2,%3};\n"
        : "+f"(d[0]),"+f"(d[1]),"+f"(d[2]),"+f"(d[3])
        : "r"(a[0]),"r"(a[1]),"r"(a[2]),"r"(a[3]), "r"(b[0]),"r"(b[1]));
}

// ---------------- elementwise kernels ------------------------------------
__global__ void gather_pe_split(const float* __restrict__ emb,
                                const float* __restrict__ pe,
                                const int*   __restrict__ idx,
                                __nv_bfloat16* __restrict__ xh,
                                __nv_bfloat16* __restrict__ xl)
{
    long i = (long)blockIdx.x * blockDim.x + threadIdx.x;
    const long n4 = (long)MR * HH / 4;
    if (i >= n4) return;
    long row = i / (HH/4);
    long c4  = i - row * (HH/4);
    float4 e = ((const float4*)emb)[i];
    const float4* p = (const float4*)(pe + (long)idx[row]*HH);
    float4 pv = p[c4];
    float v[4] = {e.x+pv.x, e.y+pv.y, e.z+pv.z, e.w+pv.w};
    __nv_bfloat16 h[4], l[4];
    #pragma unroll
    for (int j = 0; j < 4; j++) bsplit(v[j], h[j], l[j]);
    ((__nv_bfloat162*)xh)[2*i]   = __nv_bfloat162(h[0],h[1]);
    ((__nv_bfloat162*)xh)[2*i+1] = __nv_bfloat162(h[2],h[3]);
    ((__nv_bfloat162*)xl)[2*i]   = __nv_bfloat162(l[0],l[1]);
    ((__nv_bfloat162*)xl)[2*i+1] = __nv_bfloat162(l[2],l[3]);
}

__global__ void split_kernel(const float* __restrict__ x,
                             __nv_bfloat16* __restrict__ hi,
                             __nv_bfloat16* __restrict__ lo, long n4)
{
    long i = (long)blockIdx.x * blockDim.x + threadIdx.x;
    if (i >= n4) return;
    float4 v = ((const float4*)x)[i];
    __nv_bfloat16 h[4], l[4];
    bsplit(v.x,h[0],l[0]); bsplit(v.y,h[1],l[1]);
    bsplit(v.z,h[2],l[2]); bsplit(v.w,h[3],l[3]);
    ((__nv_bfloat162*)hi)[2*i]   = __nv_bfloat162(h[0],h[1]);
    ((__nv_bfloat162*)hi)[2*i+1] = __nv_bfloat162(h[2],h[3]);
    ((__nv_bfloat162*)lo)[2*i]   = __nv_bfloat162(l[0],l[1]);
    ((__nv_bfloat162*)lo)[2*i+1] = __nv_bfloat162(l[2],l[3]);
}

// transpose [HH,HH] fp32
__global__ void transpose_k(const float* __restrict__ in, float* __restrict__ out)
{
    __shared__ float t[32][33];
    int x0 = blockIdx.x*32, y0 = blockIdx.y*32;
    int tx = threadIdx.x, ty = threadIdx.y;   // (32,8)
    #pragma unroll
    for (int r = 0; r < 32; r += 8)
        t[ty+r][tx] = in[(long)(y0+ty+r)*HH + x0+tx];
    __syncthreads();
    #pragma unroll
    for (int r = 0; r < 32; r += 8)
        out[(long)(x0+ty+r)*HH + y0+tx] = t[tx][ty+r];
}

__global__ void bias_fold_k(const float* __restrict__ w,
                            const float* __restrict__ bin,
                            const float* __restrict__ badd,
                            float* __restrict__ out)
{
    int n = blockIdx.x * 8 + (threadIdx.x >> 5);
    int lane = threadIdx.x & 31;
    if (n >= HH) return;
    const float* wr = w + (long)n*HH;
    float s = 0.f;
    for (int j = lane; j < HH; j += 32) s += wr[j]*bin[j];
    #pragma unroll
    for (int o = 16; o > 0; o >>= 1) s += __shfl_xor_sync(0xffffffffu, s, o);
    if (lane == 0) out[n] = s + badd[n];
}

__global__ void ln_split_kernel(const float* __restrict__ in,
                                const float* __restrict__ g,
                                const float* __restrict__ b,
                                float* __restrict__ of,
                                __nv_bfloat16* __restrict__ oh,
                                __nv_bfloat16* __restrict__ ol)
{
    __shared__ float sh[8];
    long row = blockIdx.x;
    const float* x = in + row * (long)HH;
    int t = threadIdx.x;
    float v[8];
    float s = 0.f;
    #pragma unroll
    for (int i = 0; i < 8; i++) { v[i] = x[t + i*256]; s += v[i]; }
    #pragma unroll
    for (int o = 16; o > 0; o >>= 1) s += __shfl_xor_sync(0xffffffffu, s, o);
    if ((t & 31) == 0) sh[t >> 5] = s;
    __syncthreads();
    float mean = (sh[0]+sh[1]+sh[2]+sh[3]+sh[4]+sh[5]+sh[6]+sh[7]) * (1.f/HH);
    __syncthreads();
    float sq = 0.f;
    #pragma unroll
    for (int i = 0; i < 8; i++) { float d = v[i]-mean; sq += d*d; }
    #pragma unroll
    for (int o = 16; o > 0; o >>= 1) sq += __shfl_xor_sync(0xffffffffu, sq, o);
    if ((t & 31) == 0) sh[t >> 5] = sq;
    __syncthreads();
    float rstd = rsqrtf((sh[0]+sh[1]+sh[2]+sh[3]+sh[4]+sh[5]+sh[6]+sh[7]) * (1.f/HH) + 1e-5f);
    long base = row * (long)HH;
    #pragma unroll
    for (int i = 0; i < 8; i++) {
        int c = t + i*256;
        float y = (v[i]-mean)*rstd*g[c] + b[c];
        if (of) of[base + c] = y;
        __nv_bfloat16 h, l; bsplit(y, h, l);
        oh[base + c] = h; ol[base + c] = l;
    }
}

__global__ void l2norm_kernel(const float* __restrict__ in, float* __restrict__ out)
{
    __shared__ float sh[8];
    long row = blockIdx.x;
    const float* x = in + row * (long)HH;
    int t = threadIdx.x;
    float v[8];
    float sq = 0.f;
    #pragma unroll
    for (int i = 0; i < 8; i++) { v[i] = x[t + i*256]; sq += v[i]*v[i]; }
    #pragma unroll
    for (int o = 16; o > 0; o >>= 1) sq += __shfl_xor_sync(0xffffffffu, sq, o);
    if ((t & 31) == 0) sh[t >> 5] = sq;
    __syncthreads();
    float tot = sh[0]+sh[1]+sh[2]+sh[3]+sh[4]+sh[5]+sh[6]+sh[7];
    float inv = 1.f / fmaxf(sqrtf(tot), 1e-12f);
    float* orow = out + row * (long)HH;
    #pragma unroll
    for (int i = 0; i < 8; i++) { int c = t + i*256; orow[c] = v[i]*inv; }
}

__global__ void softmax_split(const float* __restrict__ s,
                              __nv_bfloat16* __restrict__ oh,
                              __nv_bfloat16* __restrict__ ol)
{
    long warp = ((long)blockIdx.x * blockDim.x + threadIdx.x) >> 5;
    int lane = threadIdx.x & 31;
    if (warp >= (long)NSROWS) return;
    const float* row = s + warp * (long)SS;
    float vals[16];
    float mx = -1e30f;
    #pragma unroll
    for (int i = 0; i < 16; i++) { vals[i] = row[lane + i*32]; mx = fmaxf(mx, vals[i]); }
    #pragma unroll
    for (int o = 16; o > 0; o >>= 1) mx = fmaxf(mx, __shfl_xor_sync(0xffffffffu, mx, o));
    float sum = 0.f;
    #pragma unroll
    for (int i = 0; i < 16; i++) { vals[i] = __expf(vals[i]-mx); sum += vals[i]; }
    #pragma unroll
    for (int o = 16; o > 0; o >>= 1) sum += __shfl_xor_sync(0xffffffffu, sum, o);
    float inv = 1.f / sum;
    long base = warp * (long)SS;
    #pragma unroll
    for (int i = 0; i < 16; i++) {
        float y = vals[i]*inv;
        __nv_bfloat16 h, l; bsplit(y, h, l);
        oh[base + lane + i*32] = h; ol[base + lane + i*32] = l;
    }
}

__global__ void vtrans_kernel(const __nv_bfloat16* __restrict__ qh,
                              const __nv_bfloat16* __restrict__ ql,
                              __nv_bfloat16* __restrict__ vh,
                              __nv_bfloat16* __restrict__ vl)
{
    __shared__ uint32_t tile[32][33];
    int bh = blockIdx.z;
    int b = bh >> 3, h = bh & 7;
    int s0 = blockIdx.x * 32, d0 = blockIdx.y * 32;
    int tx = threadIdx.x, ty = threadIdx.y;     // (32,8)
    long ibase = (long)b*QSTR + 2*HH + (long)h*HD;
    #pragma unroll
    for (int r = 0; r < 32; r += 8) {
        long idx = ibase + (long)(s0+ty+r)*H3 + d0+tx;
        uint32_t u = ((uint32_t)__bfloat16_as_ushort(qh[idx]) << 16)
                   |  (uint32_t)__bfloat16_as_ushort(ql[idx]);
        tile[ty+r][tx] = u;
    }
    __syncthreads();
    long obase = (long)bh * VTS;
    #pragma unroll
    for (int r = 0; r < 32; r += 8) {
        uint32_t u = tile[tx][ty+r];
        long o = obase + (long)(d0+ty+r)*SS + s0+tx;
        vh[o] = __ushort_as_bfloat16((unsigned short)(u >> 16));
        vl[o] = __ushort_as_bfloat16((unsigned short)(u & 0xffff));
    }
}

// ---------------- mma.sync bf16-split GEMM, 128x256 CTA tile -------------
// 8 warps of 64x64. 2-stage cp.async, single barrier per chunk, loads
// issued mid-chunk (after ks0). All loader offsets hoisted as uint32.
#define STG_SZ 98304
#define SM_AH 0
#define SM_AL 16384
#define SM_BH 32768
#define SM_BL 65536
#define SMEMSZ (2*STG_SZ)

template<int ACT, bool RESID, int OMODE>
__global__ void __launch_bounds__(256, 1) tc_gemm(
    const __nv_bfloat16* __restrict__ Ah, const __nv_bfloat16* __restrict__ Al,
    const __nv_bfloat16* __restrict__ Bh, const __nv_bfloat16* __restrict__ Bl,
    const float* __restrict__ bias, const float* __restrict__ Rr,
    float* __restrict__ Cf,
    __nv_bfloat16* __restrict__ Ch, __nv_bfloat16* __restrict__ Cl,
    int K, int lda, int ldb, int ldc,
    long offA1, long offA2, long offB1, long offB2, long offC1, long offC2,
    float alpha)
{
    extern __shared__ char smem[];
    uint32_t sb = (uint32_t)__cvta_generic_to_shared(smem);
    int tid = threadIdx.x;
    int z = blockIdx.z, zb = z >> 3, zh = z & 7;
    long ash = zb*offA1 + zh*offA2;
    long bsh = zb*offB1 + zh*offB2;
    long csh = zb*offC1 + zh*offC2;
    Ah += ash; Al += ash; Bh += bsh; Bl += bsh;
    long m0 = (long)blockIdx.y * 128;
    long n0 = (long)blockIdx.x * 256;

    int l = tid & 31, w = tid >> 5;
    int wm = w & 1, wn = w >> 1;        // 2 x 4 warps, each 64x64

    uint32_t a_off[4], b_off[4];
    #pragma unroll
    for (int mi = 0; mi < 4; mi++){
        int row = wm*64 + mi*16 + (l & 15);
        a_off[mi] = row*128 + (((l >> 4) << 4) ^ ((row & 7) << 4));
    }
    #pragma unroll
    for (int nj = 0; nj < 4; nj++){
        int row = wn*64 + nj*16 + (l & 7) + ((l & 16) ? 8 : 0);
        b_off[nj] = row*128 + ((((l >> 3) & 1) << 4) ^ ((row & 7) << 4));
    }

    // hoisted loader offsets (all buffers < 2^31 elements)
    uint32_t ag[4], asmo[4], bg[8], bsmo[8];
    #pragma unroll
    for (int i = 0; i < 4; i++){
        int task = tid + i*256;
        int row = task >> 3, seg = task & 7;
        asmo[i] = row*128 + ((seg*16) ^ ((row & 7) << 4));
        ag[i]   = (uint32_t)((m0 + row) * lda + seg*8);
    }
    #pragma unroll
    for (int i = 0; i < 8; i++){
        int task = tid + i*256;
        int row = task >> 3, seg = task & 7;
        bsmo[i] = row*128 + ((seg*16) ^ ((row & 7) << 4));
        bg[i]   = (uint32_t)((n0 + row) * ldb + seg*8);
    }

    float acc[4][8][4];
    #pragma unroll
    for (int a = 0; a < 4; a++)
        #pragma unroll
        for (int b = 0; b < 8; b++)
            #pragma unroll
            for (int c = 0; c < 4; c++) acc[a][b][c] = 0.f;

    const int NC = K >> 6;
    auto load_chunk = [&](int st, int kc){
        uint32_t base = sb + st*STG_SZ;
        uint32_t k0 = (uint32_t)kc << 6;
        #pragma unroll
        for (int i = 0; i < 4; i++){
            cpa16(base + SM_AH + asmo[i], Ah + ag[i] + k0);
            cpa16(base + SM_AL + asmo[i], Al + ag[i] + k0);
        }
        #pragma unroll
        for (int i = 0; i < 8; i++){
            cpa16(base + SM_BH + bsmo[i], Bh + bg[i] + k0);
            cpa16(base + SM_BL + bsmo[i], Bl + bg[i] + k0);
        }
        asm volatile("cp.async.commit_group;\n" ::: "memory");
    };

    load_chunk(0, 0);
    int st = 0;
    for (int c = 0; c < NC; c++){
        asm volatile("cp.async.wait_group 0;\n" ::: "memory");
        __syncthreads();        // all warps done with stage st^1 reads; stage st visible
        uint32_t bAh = sb + st*STG_SZ + SM_AH;
        uint32_t bAl = sb + st*STG_SZ + SM_AL;
        uint32_t bBh = sb + st*STG_SZ + SM_BH;
        uint32_t bBl = sb + st*STG_SZ + SM_BL;

        auto compute_ks = [&](int ks){
            uint32_t kx = (uint32_t)ks << 5;
            uint32_t ahf[4][4], alf[4][4], bhf[4][4], blf[4][4];
            #pragma unroll
            for (int mi = 0; mi < 4; mi++){
                ldsm4(bAh + (a_off[mi] ^ kx), ahf[mi]);
                ldsm4(bAl + (a_off[mi] ^ kx), alf[mi]);
            }
            #pragma unroll
            for (int nj = 0; nj < 4; nj++){
                ldsm4(bBh + (b_off[nj] ^ kx), bhf[nj]);
                ldsm4(bBl + (b_off[nj] ^ kx), blf[nj]);
            }
            #pragma unroll
            for (int mi = 0; mi < 4; mi++)
                #pragma unroll
                for (int nj = 0; nj < 8; nj++){
                    const uint32_t* b2h = &bhf[nj>>1][(nj&1)*2];
                    const uint32_t* b2l = &blf[nj>>1][(nj&1)*2];
                    mma16816(acc[mi][nj], ahf[mi], b2h);
                    mma16816(acc[mi][nj], alf[mi], b2h);
                    mma16816(acc[mi][nj], ahf[mi], b2l);
                }
        };
        compute_ks(0);
        if (c + 1 < NC) load_chunk(st ^ 1, c + 1);   // overlapped with MMAs
        compute_ks(1);
        compute_ks(2);
        compute_ks(3);
        st ^= 1;
    }

    // epilogue
    int r0 = (int)m0 + wm*64 + (l >> 2);
    int c0 = (int)n0 + wn*64 + 2*(l & 3);
    #pragma unroll
    for (int mi = 0; mi < 4; mi++){
        #pragma unroll
        for (int half = 0; half < 2; half++){
            long row = r0 + mi*16 + half*8;
            #pragma unroll
            for (int nj = 0; nj < 8; nj++){
                int cc = c0 + nj*8;
                long o = csh + row*(long)ldc + cc;
                float v0 = acc[mi][nj][half*2+0] * alpha;
                float v1 = acc[mi][nj][half*2+1] * alpha;
                if (bias){ v0 += bias[cc]; v1 += bias[cc+1]; }
                if (ACT == 1){
                    v0 = 0.5f*v0*(1.f + erff(v0*0.70710678118654752f));
                    v1 = 0.5f*v1*(1.f + erff(v1*0.70710678118654752f));
                } else if (ACT == 2){
                    v0 = fmaxf(v0, 0.f); v1 = fmaxf(v1, 0.f);
                }
                if (RESID){
                    const float* rp = Rr + o;
                    v0 += rp[0]; v1 += rp[1];
                }
                if (OMODE == 0){
                    *(float2*)(Cf + o) = make_float2(v0, v1);
                } else {
                    __nv_bfloat16 h0,l0,h1,l1;
                    bsplit(v0,h0,l0); bsplit(v1,h1,l1);
                    *(__nv_bfloat162*)(Ch + o) = __nv_bfloat162(h0,h1);
                    *(__nv_bfloat162*)(Cl + o) = __nv_bfloat162(l0,l1);
                }
            }
        }
    }
}

// ---------------- host orchestration -------------------------------------
extern "C" void kernel_launch(void* const* d_in, const int* in_sizes, int n_in,
                              void* d_out, int out_size)
{
    (void)in_sizes; (void)n_in; (void)out_size;
    const float* emb  = (const float*)d_in[0];
    const int*   tidx = (const int*)  d_in[1];
    const float* pe   = (const float*)d_in[2];
    const float* inw  = (const float*)d_in[3];
    const float* inb  = (const float*)d_in[4];
    const float* ow   = (const float*)d_in[5];
    const float* ob   = (const float*)d_in[6];
    const float* ln1g = (const float*)d_in[7];
    const float* ln1b = (const float*)d_in[8];
    const float* f1w  = (const float*)d_in[9];
    const float* f1b  = (const float*)d_in[10];
    const float* f2w  = (const float*)d_in[11];
    const float* f2b  = (const float*)d_in[12];
    const float* ln2g = (const float*)d_in[13];
    const float* ln2b = (const float*)d_in[14];
    const float* te1w = (const float*)d_in[15];
    const float* te1b = (const float*)d_in[16];
    const float* te2w = (const float*)d_in[17];
    const float* te2b = (const float*)d_in[18];
    const float* pr1w = (const float*)d_in[19];
    const float* pr1b = (const float*)d_in[20];
    const float* pr2w = (const float*)d_in[21];
    const float* pr2b = (const float*)d_in[22];
    float* out = (float*)d_out;

    float *sc,*t1,*t2,*h1,*fb;
    __nv_bfloat16 *pAh,*pAl,*pBh,*pBl,*vh,*vl,*wh,*wl,*fwh,*fwl;
    cudaGetSymbolAddress((void**)&sc,  g_sc);
    cudaGetSymbolAddress((void**)&t1,  g_t1);
    cudaGetSymbolAddress((void**)&t2,  g_t2);
    cudaGetSymbolAddress((void**)&h1,  g_h1);
    cudaGetSymbolAddress((void**)&pAh, g_pAh);
    cudaGetSymbolAddress((void**)&pAl, g_pAl);
    cudaGetSymbolAddress((void**)&pBh, g_pBh);
    cudaGetSymbolAddress((void**)&pBl, g_pBl);
    cudaGetSymbolAddress((void**)&vh,  g_vh);
    cudaGetSymbolAddress((void**)&vl,  g_vl);
    cudaGetSymbolAddress((void**)&wh,  g_wh);
    cudaGetSymbolAddress((void**)&wl,  g_wl);
    cudaGetSymbolAddress((void**)&fwh, g_fwh);
    cudaGetSymbolAddress((void**)&fwl, g_fwl);
    cudaGetSymbolAddress((void**)&fb,  g_fb);

    cudaFuncSetAttribute(tc_gemm<0,false,1>, cudaFuncAttributeMaxDynamicSharedMemorySize, SMEMSZ);
    cudaFuncSetAttribute(tc_gemm<0,false,0>, cudaFuncAttributeMaxDynamicSharedMemorySize, SMEMSZ);
    cudaFuncSetAttribute(tc_gemm<0,true ,0>, cudaFuncAttributeMaxDynamicSharedMemorySize, SMEMSZ);
    cudaFuncSetAttribute(tc_gemm<1,false,1>, cudaFuncAttributeMaxDynamicSharedMemorySize, SMEMSZ);
    cudaFuncSetAttribute(tc_gemm<2,false,1>, cudaFuncAttributeMaxDynamicSharedMemorySize, SMEMSZ);

    auto wsplit = [&](const float* src, long n){
        split_kernel<<<(unsigned)((n/4 + 255) / 256), 256>>>(src, wh, wl, n/4);
    };

    // 0) Fold te2 into pr1: W'' = pr_w1 @ te_w2, b'' = pr_w1@te_b2 + pr_b1
    transpose_k<<<dim3(64,64), dim3(32,8)>>>(te2w, t1);      // t1 = te_w2^T
    split_kernel<<<(unsigned)(((long)HH*HH/4 + 255)/256), 256>>>(t1, vh, vl, (long)HH*HH/4);
    wsplit(pr1w, (long)HH*HH);
    tc_gemm<0,false,1><<<dim3(HH/256, HH/128, 1), 256, SMEMSZ>>>(
        wh, wl, vh, vl, 0, 0, 0, fwh, fwl,
        HH, HH, HH, HH, 0,0,0,0,0,0, 1.f);
    bias_fold_k<<<HH/8, 256>>>(pr1w, te2b, pr1b, fb);

    // 1) x = emb + pe[idx]  -> poolB
    gather_pe_split<<<(MR*(HH/4) + 255)/256, 256>>>(emb, pe, tidx, pBh, pBl);

    // 2) qkv = x @ in_proj_w^T + b  -> poolA (hi/lo)
    wsplit(inw, (long)H3*HH);
    tc_gemm<0,false,1><<<dim3(H3/256, MR/128, 1), 256, SMEMSZ>>>(
        pBh, pBl, wh, wl, inb, 0, 0, pAh, pAl,
        HH, HH, HH, H3, 0,0,0,0,0,0, 1.f);

    // 3) scores = (Q@K^T)/16 -> fp32 sc   (batched over 256 heads)
    tc_gemm<0,false,0><<<dim3(SS/256, SS/128, NHEADS), 256, SMEMSZ>>>(
        pAh, pAl, pAh + HH, pAl + HH, 0, 0, sc, 0, 0,
        HD, H3, H3, SS, QSTR, HD, QSTR, HD, 8*SCH, SCH, 0.0625f);

    // 4) Vt transpose (from qkv hi/lo), softmax -> poolB
    vtrans_kernel<<<dim3(SS/32, HD/32, NHEADS), dim3(32,8)>>>(pAh, pAl, vh, vl);
    softmax_split<<<NSROWS/8, 256>>>(sc, pBh, pBl);

    // 5) o = A @ V -> poolA (hi/lo)
    tc_gemm<0,false,1><<<dim3(HD/256, SS/128, NHEADS), 256, SMEMSZ>>>(
        pBh, pBl, vh, vl, 0, 0, 0, pAh, pAl,
        SS, SS, SS, HH, 8*SCH, SCH, 8*VTS, VTS, (long)SS*HH, HD, 1.f);

    // 6) t1 = o @ out_proj_w^T + b + emb -> fp32
    wsplit(ow, (long)HH*HH);
    tc_gemm<0,true,0><<<dim3(HH/256, MR/128, 1), 256, SMEMSZ>>>(
        pAh, pAl, wh, wl, ob, emb, t1, 0, 0,
        HH, HH, HH, HH, 0,0,0,0,0,0, 1.f);

    // 7) h1 = LN(t1) -> fp32 (residual) + poolB (hi/lo)
    ln_split_kernel<<<MR, 256>>>(t1, ln1g, ln1b, h1, pBh, pBl);

    // 8) mid = gelu(h1 @ ffn_w1^T + b1) -> poolA (hi/lo)
    wsplit(f1w, (long)H4*HH);
    tc_gemm<1,false,1><<<dim3(H4/256, MR/128, 1), 256, SMEMSZ>>>(
        pBh, pBl, wh, wl, f1b, 0, 0, pAh, pAl,
        HH, HH, HH, H4, 0,0,0,0,0,0, 1.f);

    // 9) t2 = mid @ ffn_w2^T + b2 + h1 -> fp32
    wsplit(f2w, (long)HH*H4);
    tc_gemm<0,true,0><<<dim3(HH/256, MR/128, 1), 256, SMEMSZ>>>(
        pAh, pAl, wh, wl, f2b, h1, t2, 0, 0,
        H4, H4, H4, HH, 0,0,0,0,0,0, 1.f);

    // 10) h2 = LN(t2) -> poolB (hi/lo only)
    ln_split_kernel<<<MR, 256>>>(t2, ln2g, ln2b, 0, pBh, pBl);

    // 11) r1 = relu(h2 @ te_w1^T + b1) -> poolA
    wsplit(te1w, (long)HH*HH);
    tc_gemm<2,false,1><<<dim3(HH/256, MR/128, 1), 256, SMEMSZ>>>(
        pBh, pBl, wh, wl, te1b, 0, 0, pAh, pAl,
        HH, HH, HH, HH, 0,0,0,0,0,0, 1.f);

    // 12) r2 = relu(r1 @ W''^T + b'')  [te2+pr1 folded] -> poolB
    tc_gemm<2,false,1><<<dim3(HH/256, MR/128, 1), 256, SMEMSZ>>>(
        pAh, pAl, fwh, fwl, fb, 0, 0, pBh, pBl,
        HH, HH, HH, HH, 0,0,0,0,0,0, 1.f);

    // 13) pr2 -> fp32 t1
    wsplit(pr2w, (long)HH*HH);
    tc_gemm<0,false,0><<<dim3(HH/256, MR/128, 1), 256, SMEMSZ>>>(
        pBh, pBl, wh, wl, pr2b, 0, t1, 0, 0,
        HH, HH, HH, HH, 0,0,0,0,0,0, 1.f);

    // 14) out = pr / max(||pr||, 1e-12)
    l2norm_kernel<<<MR, 256>>>(t1, out);
}